// round 1
// baseline (speedup 1.0000x reference)
#include <cuda_runtime.h>
#include <math.h>

// ---------------------------------------------------------------------------
// LatentMixer: fused latent cross-attention block.
// B=8, C=512, H=W=64 (N=4096), heads=8, d=64, L=16, scale=0.125, eps=1e-12
// ---------------------------------------------------------------------------

#define Bsz 8
#define C   512
#define NPIX 4096
#define L   16
#define HEADS 8
#define DH  64
#define SCALE 0.125f
#define EPSN 1e-12f

// Scratch (device globals: allocation-free contract)
__device__ float g_kvx[(long)Bsz * 2 * C * NPIX];   // 134 MB: kx rows [0,512), vx rows [512,1024)
__device__ float g_qx [(long)Bsz * C * NPIX];       // 67 MB
__device__ float g_xw [(long)Bsz * C * NPIX];       // 67 MB
__device__ float g_attn[(long)Bsz * HEADS * L * NPIX]; // 16.8 MB (unnormalized exp)
__device__ float g_qlhat[C * L];                    // normalized latent queries (batch-invariant)
__device__ float g_latread[Bsz * C * L];
__device__ float g_kvl[Bsz * 2 * C * L];            // kl (normalized) rows [0,512), vl rows [512,1024)

// ---------------------------------------------------------------------------
// SGEMM: C[b] = A (MxK, row-major) * B[b] (KxN, row-major) (+ bias)
// BM=128, BN=64, BK=16, 256 threads, 8x4 register tile.
// ---------------------------------------------------------------------------
__global__ __launch_bounds__(256) void sgemm_kernel(
    const float* __restrict__ A, const float* __restrict__ Bm,
    float* __restrict__ Cm, const float* __restrict__ bias,
    int M, int K, int Nn, int hasBias)
{
    const float* Bp = Bm + (long)blockIdx.z * K * Nn;
    float* Cp = Cm + (long)blockIdx.z * M * Nn;
    int m0 = blockIdx.y * 128, n0 = blockIdx.x * 64;

    __shared__ float As[16][128];
    __shared__ float Bs[16][64];

    int tid = threadIdx.x;
    int tx = tid & 15, ty = tid >> 4;

    int arow = tid >> 2;          // 0..63
    int ak   = (tid & 3) * 4;     // 0,4,8,12
    int bk   = tid >> 4;          // 0..15
    int bn   = (tid & 15) * 4;    // 0..60

    float acc[8][4];
    #pragma unroll
    for (int i = 0; i < 8; i++)
        #pragma unroll
        for (int j = 0; j < 4; j++) acc[i][j] = 0.f;

    for (int k0 = 0; k0 < K; k0 += 16) {
        float4 a0 = *(const float4*)&A[(long)(m0 + arow) * K + k0 + ak];
        float4 a1 = *(const float4*)&A[(long)(m0 + arow + 64) * K + k0 + ak];
        As[ak + 0][arow] = a0.x; As[ak + 1][arow] = a0.y;
        As[ak + 2][arow] = a0.z; As[ak + 3][arow] = a0.w;
        As[ak + 0][arow + 64] = a1.x; As[ak + 1][arow + 64] = a1.y;
        As[ak + 2][arow + 64] = a1.z; As[ak + 3][arow + 64] = a1.w;
        *(float4*)&Bs[bk][bn] = *(const float4*)&Bp[(long)(k0 + bk) * Nn + n0 + bn];
        __syncthreads();

        #pragma unroll
        for (int kk = 0; kk < 16; kk++) {
            float4 b03 = *(const float4*)&Bs[kk][tx * 4];
            float4 a03 = *(const float4*)&As[kk][ty * 8];
            float4 a47 = *(const float4*)&As[kk][ty * 8 + 4];
            float av[8] = {a03.x, a03.y, a03.z, a03.w, a47.x, a47.y, a47.z, a47.w};
            float bv[4] = {b03.x, b03.y, b03.z, b03.w};
            #pragma unroll
            for (int i = 0; i < 8; i++)
                #pragma unroll
                for (int j = 0; j < 4; j++) acc[i][j] += av[i] * bv[j];
        }
        __syncthreads();
    }

    #pragma unroll
    for (int i = 0; i < 8; i++) {
        int m = m0 + ty * 8 + i;
        float bb = hasBias ? bias[m] : 0.f;
        float4 r = make_float4(acc[i][0] + bb, acc[i][1] + bb, acc[i][2] + bb, acc[i][3] + bb);
        *(float4*)&Cp[(long)m * Nn + n0 + tx * 4] = r;
    }
}

// ---------------------------------------------------------------------------
// qlhat: ql = w_q_lat @ latents (512x16), then L2-normalize per (head, l) over d.
// Batch-invariant. grid=8 (one block per head), 256 threads.
// ---------------------------------------------------------------------------
__global__ __launch_bounds__(256) void qlhat_kernel(
    const float* __restrict__ w_q_lat, const float* __restrict__ latents,
    float* __restrict__ qlhat)
{
    int h = blockIdx.x;
    __shared__ float slat[C][L];
    __shared__ float stile[DH][L];
    __shared__ float snorm[L];
    int tid = threadIdx.x;
    for (int i = tid; i < C * L; i += 256) slat[i >> 4][i & 15] = latents[i];
    __syncthreads();
    for (int p = tid; p < DH * L; p += 256) {
        int j = p >> 4, l = p & 15;
        const float* wrow = w_q_lat + (long)(h * DH + j) * C;
        float acc = 0.f;
        for (int c2 = 0; c2 < C; c2++) acc += wrow[c2] * slat[c2][l];
        stile[j][l] = acc;
    }
    __syncthreads();
    if (tid < L) {
        float s = 0.f;
        for (int j = 0; j < DH; j++) { float v = stile[j][tid]; s += v * v; }
        snorm[tid] = 1.f / fmaxf(sqrtf(s), EPSN);
    }
    __syncthreads();
    for (int p = tid; p < DH * L; p += 256)
        qlhat[(h * DH + (p >> 4)) * L + (p & 15)] = stile[p >> 4][p & 15] * snorm[p & 15];
}

// ---------------------------------------------------------------------------
// Attention 1 (latent read): per (b,h): logits = qlhat^T khat * scale,
// softmax over N=4096 (logits bounded by scale -> no max pass),
// lat_read = vx @ p. One block per (b,h), 512 threads.
// ---------------------------------------------------------------------------
__global__ __launch_bounds__(512) void attn1_kernel(
    const float* __restrict__ kvx, const float* __restrict__ qlhat,
    float* __restrict__ attn_g, float* __restrict__ latread)
{
    int bh = blockIdx.x, b = bh >> 3, h = bh & 7;
    const float* kbase = kvx + ((long)b * 2 * C + h * DH) * NPIX;
    const float* vbase = kvx + ((long)b * 2 * C + C + h * DH) * NPIX;
    float* attn = attn_g + (long)bh * L * NPIX;

    __shared__ float sql[DH][L];
    __shared__ float wred[16][L];
    __shared__ float sinv[L];

    int tid = threadIdx.x;
    for (int i = tid; i < DH * L; i += 512)
        sql[i >> 4][i & 15] = qlhat[(h * DH + (i >> 4)) * L + (i & 15)];
    __syncthreads();

    float lsum[L];
    #pragma unroll
    for (int l = 0; l < L; l++) lsum[l] = 0.f;

    // phase 1: logits -> exp -> scratch, accumulate per-l sums. 4 columns/thread/pass.
    #pragma unroll
    for (int half = 0; half < 2; half++) {
        int n = tid + half * 2048;
        float dot[4][L];
        float nrm[4] = {0.f, 0.f, 0.f, 0.f};
        #pragma unroll
        for (int c = 0; c < 4; c++)
            #pragma unroll
            for (int l = 0; l < L; l++) dot[c][l] = 0.f;
        for (int j = 0; j < DH; j++) {
            float kv[4];
            #pragma unroll
            for (int c = 0; c < 4; c++) {
                kv[c] = kbase[(long)j * NPIX + n + c * 512];
                nrm[c] += kv[c] * kv[c];
            }
            #pragma unroll
            for (int l = 0; l < L; l++) {
                float s = sql[j][l];
                #pragma unroll
                for (int c = 0; c < 4; c++) dot[c][l] += kv[c] * s;
            }
        }
        #pragma unroll
        for (int c = 0; c < 4; c++) {
            float inv = SCALE / fmaxf(sqrtf(nrm[c]), EPSN);
            #pragma unroll
            for (int l = 0; l < L; l++) {
                float p = __expf(dot[c][l] * inv);
                lsum[l] += p;
                attn[(long)l * NPIX + n + c * 512] = p;
            }
        }
    }

    // block-reduce lsum
    int lane = tid & 31, wrp = tid >> 5;
    #pragma unroll
    for (int l = 0; l < L; l++) {
        float v = lsum[l];
        #pragma unroll
        for (int o = 16; o; o >>= 1) v += __shfl_xor_sync(0xffffffffu, v, o);
        if (lane == 0) wred[wrp][l] = v;
    }
    __syncthreads();
    if (tid < L) {
        float s = 0.f;
        for (int w2 = 0; w2 < 16; w2++) s += wred[w2][tid];
        sinv[tid] = 1.f / s;
    }
    __syncthreads();

    // phase 2: out[j][l] = sinv[l] * sum_n p[l][n] * v[j][n]; warp wrp owns j in [4w, 4w+4)
    float acc[4][L];
    #pragma unroll
    for (int jj = 0; jj < 4; jj++)
        #pragma unroll
        for (int l = 0; l < L; l++) acc[jj][l] = 0.f;
    for (int n = lane; n < NPIX; n += 32) {
        float pv[L];
        #pragma unroll
        for (int l = 0; l < L; l++) pv[l] = attn[(long)l * NPIX + n];
        #pragma unroll
        for (int jj = 0; jj < 4; jj++) {
            float v = vbase[(long)(wrp * 4 + jj) * NPIX + n];
            #pragma unroll
            for (int l = 0; l < L; l++) acc[jj][l] += v * pv[l];
        }
    }
    #pragma unroll
    for (int jj = 0; jj < 4; jj++)
        #pragma unroll
        for (int l = 0; l < L; l++) {
            float v = acc[jj][l];
            #pragma unroll
            for (int o = 16; o; o >>= 1) v += __shfl_xor_sync(0xffffffffu, v, o);
            if (lane == 0)
                latread[((long)b * C + h * DH + wrp * 4 + jj) * L + l] = v * sinv[l];
        }
}

// ---------------------------------------------------------------------------
// kvl: kvl[b] = w_kv_lat (1024x512) @ lat_read[b] (512x16); normalize k-part
// per (head,l) over d. grid (B, 16 row-chunks of 64), 256 threads.
// ---------------------------------------------------------------------------
__global__ __launch_bounds__(256) void kvl_kernel(
    const float* __restrict__ w_kv_lat, const float* __restrict__ latread,
    float* __restrict__ kvl)
{
    int b = blockIdx.x, c0 = blockIdx.y * 64;
    __shared__ float slat[C][L];
    __shared__ float stile[64][L];
    __shared__ float snorm[L];
    int tid = threadIdx.x;
    const float* lr = latread + (long)b * C * L;
    for (int i = tid; i < C * L; i += 256) slat[i >> 4][i & 15] = lr[i];
    __syncthreads();
    for (int p = tid; p < 64 * L; p += 256) {
        int j = p >> 4, l = p & 15;
        const float* wrow = w_kv_lat + (long)(c0 + j) * C;
        float acc = 0.f;
        for (int c2 = 0; c2 < C; c2++) acc += wrow[c2] * slat[c2][l];
        stile[j][l] = acc;
    }
    __syncthreads();
    if (c0 < C) {  // k-part: chunk == one head's d exactly
        if (tid < L) {
            float s = 0.f;
            for (int j = 0; j < 64; j++) { float v = stile[j][tid]; s += v * v; }
            snorm[tid] = 1.f / fmaxf(sqrtf(s), EPSN);
        }
        __syncthreads();
        for (int p = tid; p < 64 * L; p += 256)
            kvl[((long)b * 2 * C + c0 + (p >> 4)) * L + (p & 15)] =
                stile[p >> 4][p & 15] * snorm[p & 15];
    } else {
        for (int p = tid; p < 64 * L; p += 256)
            kvl[((long)b * 2 * C + c0 + (p >> 4)) * L + (p & 15)] = stile[p >> 4][p & 15];
    }
}

// ---------------------------------------------------------------------------
// Attention 2 (latent write), fully fused per pixel: for each (b,n,h):
// normalize qx column, 16 logits vs klhat, softmax over L=16, combine vl.
// 128 threads, 2 pixels/thread (256 px/block); grid (16, B).
// ---------------------------------------------------------------------------
__global__ __launch_bounds__(128) void attn2_kernel(
    const float* __restrict__ qx, const float* __restrict__ kvl,
    float* __restrict__ xw)
{
    int b = blockIdx.y;
    int n = blockIdx.x * 256 + threadIdx.x;  // pixels n and n+128
    __shared__ float skl[DH][L];
    __shared__ float svl[DH][L];
    const float* kvlb = kvl + (long)b * 2 * C * L;

    for (int h = 0; h < HEADS; h++) {
        __syncthreads();
        for (int i = threadIdx.x; i < DH * L; i += 128) {
            skl[i >> 4][i & 15] = kvlb[(h * DH + (i >> 4)) * L + (i & 15)];
            svl[i >> 4][i & 15] = kvlb[(C + h * DH + (i >> 4)) * L + (i & 15)];
        }
        __syncthreads();

        const float* qcol = qx + ((long)b * C + h * DH) * NPIX + n;
        float dot[2][L];
        float nrm[2] = {0.f, 0.f};
        #pragma unroll
        for (int c = 0; c < 2; c++)
            #pragma unroll
            for (int l = 0; l < L; l++) dot[c][l] = 0.f;
        for (int j = 0; j < DH; j++) {
            float q0 = qcol[(long)j * NPIX];
            float q1 = qcol[(long)j * NPIX + 128];
            nrm[0] += q0 * q0; nrm[1] += q1 * q1;
            #pragma unroll
            for (int l = 0; l < L; l++) {
                float s = skl[j][l];
                dot[0][l] += q0 * s;
                dot[1][l] += q1 * s;
            }
        }
        float is[2];
        #pragma unroll
        for (int c = 0; c < 2; c++) {
            float inv = SCALE / fmaxf(sqrtf(nrm[c]), EPSN);
            float s = 0.f;
            #pragma unroll
            for (int l = 0; l < L; l++) { dot[c][l] = __expf(dot[c][l] * inv); s += dot[c][l]; }
            is[c] = 1.f / s;
        }
        float* xcol = xw + ((long)b * C + h * DH) * NPIX + n;
        for (int j = 0; j < DH; j++) {
            float a0 = 0.f, a1 = 0.f;
            #pragma unroll
            for (int l = 0; l < L; l++) {
                float v = svl[j][l];
                a0 += dot[0][l] * v;
                a1 += dot[1][l] * v;
            }
            xcol[(long)j * NPIX] = a0 * is[0];
            xcol[(long)j * NPIX + 128] = a1 * is[1];
        }
    }
}

// ---------------------------------------------------------------------------
// Launch
// ---------------------------------------------------------------------------
extern "C" void kernel_launch(void* const* d_in, const int* in_sizes, int n_in,
                              void* d_out, int out_size)
{
    const float* x        = (const float*)d_in[0];
    const float* latents  = (const float*)d_in[1];
    const float* w_q_lat  = (const float*)d_in[2];
    const float* w_kv_x   = (const float*)d_in[3];
    const float* w_q_x    = (const float*)d_in[4];
    const float* w_kv_lat = (const float*)d_in[5];
    const float* w_proj   = (const float*)d_in[6];
    const float* b_proj   = (const float*)d_in[7];
    float* out = (float*)d_out;

    float *kvx, *qx, *xw, *attn, *qlhat, *latread, *kvl;
    cudaGetSymbolAddress((void**)&kvx, g_kvx);
    cudaGetSymbolAddress((void**)&qx, g_qx);
    cudaGetSymbolAddress((void**)&xw, g_xw);
    cudaGetSymbolAddress((void**)&attn, g_attn);
    cudaGetSymbolAddress((void**)&qlhat, g_qlhat);
    cudaGetSymbolAddress((void**)&latread, g_latread);
    cudaGetSymbolAddress((void**)&kvl, g_kvl);

    // latent queries (batch-invariant)
    qlhat_kernel<<<HEADS, 256>>>(w_q_lat, latents, qlhat);
    // kvx = w_kv_x @ x ; qx = w_q_x @ x
    sgemm_kernel<<<dim3(NPIX / 64, (2 * C) / 128, Bsz), 256>>>(w_kv_x, x, kvx, nullptr, 2 * C, C, NPIX, 0);
    sgemm_kernel<<<dim3(NPIX / 64, C / 128, Bsz), 256>>>(w_q_x, x, qx, nullptr, C, C, NPIX, 0);
    // latent read attention
    attn1_kernel<<<Bsz * HEADS, 512>>>(kvx, qlhat, attn, latread);
    // kvl = w_kv_lat @ lat_read (+ k normalization)
    kvl_kernel<<<dim3(Bsz, 16), 256>>>(w_kv_lat, latread, kvl);
    // latent write attention (fused per pixel)
    attn2_kernel<<<dim3(16, Bsz), 128>>>(qx, kvl, xw);
    // output projection + bias
    sgemm_kernel<<<dim3(NPIX / 64, C / 128, Bsz), 256>>>(w_proj, xw, out, b_proj, C, C, NPIX, 1);
}

// round 4
// speedup vs baseline: 2.2863x; 2.2863x over previous
#include <cuda_runtime.h>
#include <cuda_bf16.h>
#include <math.h>
#include <stdint.h>

// ---------------------------------------------------------------------------
// LatentMixer on GB300 (sm_103 non-'a' target): HMMA mma.sync bf16-split GEMMs
// + fused attention. B=8, C=512, N=4096, heads=8, d=64, L=16, scale=0.125
// ---------------------------------------------------------------------------

#define Bsz 8
#define C   512
#define NPIX 4096
#define L   16
#define HEADS 8
#define DH  64
#define SCALE 0.125f
#define EPSN 1e-12f
#define KDIM 512

// ---------------- scratch (device globals; allocation-free contract) -------
__device__ float g_kvx[(size_t)Bsz * 2 * C * NPIX];
__device__ float g_qx [(size_t)Bsz * C * NPIX];
__device__ float g_attn[(size_t)Bsz * HEADS * L * NPIX];
__device__ float g_lsum[64 * 4 * L];
__device__ float g_sinv[64 * L];
__device__ float g_latpart[4 * 64 * DH * L];
__device__ float g_latread[Bsz * C * L];
__device__ float g_kvl[Bsz * 2 * C * L];
__device__ float g_qlhat[C * L];
__device__ __nv_bfloat16 g_xThi[(size_t)Bsz * NPIX * C];
__device__ __nv_bfloat16 g_xTlo[(size_t)Bsz * NPIX * C];
__device__ __nv_bfloat16 g_xwThi[(size_t)Bsz * NPIX * C];
__device__ __nv_bfloat16 g_xwTlo[(size_t)Bsz * NPIX * C];
__device__ __nv_bfloat16 g_wkvhi[2 * C * KDIM], g_wkvlo[2 * C * KDIM];
__device__ __nv_bfloat16 g_wqhi[C * KDIM],      g_wqlo[C * KDIM];
__device__ __nv_bfloat16 g_wphi[C * KDIM],      g_wplo[C * KDIM];

// ---------------- helpers ---------------------------------------------------
__device__ __forceinline__ uint32_t smem_u32(const void* p) {
    uint32_t a;
    asm("{ .reg .u64 t; cvta.to.shared.u64 t, %1; cvt.u32.u64 %0, t; }" : "=r"(a) : "l"(p));
    return a;
}

#define LDSM4(r, addr) \
    asm volatile("ldmatrix.sync.aligned.m8n8.x4.shared.b16 {%0,%1,%2,%3}, [%4];" \
                 : "=r"((r)[0]), "=r"((r)[1]), "=r"((r)[2]), "=r"((r)[3]) : "r"(addr))

#define MMA16816(cc, aa, b0, b1) \
    asm volatile("mma.sync.aligned.m16n8k16.row.col.f32.bf16.bf16.f32 " \
                 "{%0,%1,%2,%3}, {%4,%5,%6,%7}, {%8,%9}, {%0,%1,%2,%3};" \
                 : "+f"((cc)[0]), "+f"((cc)[1]), "+f"((cc)[2]), "+f"((cc)[3]) \
                 : "r"((aa)[0]), "r"((aa)[1]), "r"((aa)[2]), "r"((aa)[3]), \
                   "r"(b0), "r"(b1))

#define CP_ASYNC16(dst, src) \
    asm volatile("cp.async.cg.shared.global [%0], [%1], 16;" :: "r"(dst), "l"(src))
#define CP_COMMIT() asm volatile("cp.async.commit_group;" ::: "memory")
#define CP_WAIT(n)  asm volatile("cp.async.wait_group %0;" :: "n"(n) : "memory")

// ---------------------------------------------------------------------------
// Weight split: fp32 -> bf16 hi + bf16 lo
// ---------------------------------------------------------------------------
__global__ __launch_bounds__(256) void wsplit_kernel(
    const float* __restrict__ a, __nv_bfloat16* __restrict__ hi,
    __nv_bfloat16* __restrict__ lo, int n4)
{
    int i = blockIdx.x * 256 + threadIdx.x;
    if (i >= n4) return;
    float4 v = ((const float4*)a)[i];
    float f[4] = {v.x, v.y, v.z, v.w};
    #pragma unroll
    for (int j = 0; j < 4; j++) {
        __nv_bfloat16 h = __float2bfloat16_rn(f[j]);
        hi[i * 4 + j] = h;
        lo[i * 4 + j] = __float2bfloat16_rn(f[j] - __bfloat162float(h));
    }
}

// ---------------------------------------------------------------------------
// Transpose + split x: [B,C,N] fp32 -> [B,N,C] bf16 hi/lo. 32x32 tiles.
// ---------------------------------------------------------------------------
__global__ __launch_bounds__(256) void tsplit_kernel(
    const float* __restrict__ x, __nv_bfloat16* __restrict__ hi,
    __nv_bfloat16* __restrict__ lo)
{
    __shared__ float t[32][33];
    int n0 = blockIdx.x * 32, c0 = blockIdx.y * 32, b = blockIdx.z;
    int tx = threadIdx.x, ty = threadIdx.y;
    const float* xb = x + (size_t)b * C * NPIX;
    #pragma unroll
    for (int i = 0; i < 4; i++)
        t[ty + i * 8][tx] = xb[(size_t)(c0 + ty + i * 8) * NPIX + n0 + tx];
    __syncthreads();
    __nv_bfloat16* hb = hi + (size_t)b * NPIX * C;
    __nv_bfloat16* lb = lo + (size_t)b * NPIX * C;
    #pragma unroll
    for (int i = 0; i < 4; i++) {
        float v = t[tx][ty + i * 8];
        __nv_bfloat16 h = __float2bfloat16_rn(v);
        size_t o = (size_t)(n0 + ty + i * 8) * C + c0 + tx;
        hb[o] = h;
        lb[o] = __float2bfloat16_rn(v - __bfloat162float(h));
    }
}

// ---------------------------------------------------------------------------
// HMMA GEMM: Cout[z][m][n] = sum_k A[m][k]*B[z][n][k], 3-term bf16 split.
// A: [M,512] hi/lo K-major; B: [B,4096,512] hi/lo K-major.
// Tile 128x128x64, 256 threads (2x4 warps, warp tile 64x32), 3-stage cp.async.
// smem stage: Ahi(16K) Alo(16K) Bhi(16K) Blo(16K), SW128 swizzle (128B rows).
// ---------------------------------------------------------------------------
#define STG 65536
__device__ __forceinline__ void gemm_load_stage(
    char* sm, int stg, int ck, int tid,
    const __nv_bfloat16* a0, const __nv_bfloat16* a1,
    const __nv_bfloat16* b0, const __nv_bfloat16* b1)
{
    char* d = sm + stg * STG;
    #pragma unroll
    for (int i = 0; i < 16; i++) {
        int u = tid + i * 256;
        int r = u >> 10, idx = u & 1023, row = idx >> 3, c = idx & 7;
        const __nv_bfloat16* src =
            ((r == 0) ? a0 : (r == 1) ? a1 : (r == 2) ? b0 : b1)
            + (size_t)row * KDIM + ck * 64 + c * 8;
        uint32_t dst = smem_u32(d + r * 16384 + row * 128 + (((c ^ (row & 7))) << 4));
        CP_ASYNC16(dst, src);
    }
    CP_COMMIT();
}

__global__ __launch_bounds__(256) void gemm_mma(
    const __nv_bfloat16* __restrict__ Ahi, const __nv_bfloat16* __restrict__ Alo,
    const __nv_bfloat16* __restrict__ Bhi, const __nv_bfloat16* __restrict__ Blo,
    float* __restrict__ Cout, const float* __restrict__ bias, int M)
{
    extern __shared__ char sm[];
    int tid = threadIdx.x, lane = tid & 31, wid = tid >> 5;
    int wm = wid >> 2, wn = wid & 3;            // 2 x 4 warps
    int m0 = blockIdx.y * 128, n0 = blockIdx.x * 128, z = blockIdx.z;

    const __nv_bfloat16* a0p = Ahi + (size_t)m0 * KDIM;
    const __nv_bfloat16* a1p = Alo + (size_t)m0 * KDIM;
    const __nv_bfloat16* b0p = Bhi + ((size_t)z * NPIX + n0) * KDIM;
    const __nv_bfloat16* b1p = Blo + ((size_t)z * NPIX + n0) * KDIM;

    float acc[4][4][4];
    #pragma unroll
    for (int i = 0; i < 4; i++)
        #pragma unroll
        for (int j = 0; j < 4; j++)
            #pragma unroll
            for (int k = 0; k < 4; k++) acc[i][j][k] = 0.f;

    gemm_load_stage(sm, 0, 0, tid, a0p, a1p, b0p, b1p);
    gemm_load_stage(sm, 1, 1, tid, a0p, a1p, b0p, b1p);

    // precomputed ldmatrix address components
    int a_row = wm * 64 + ((lane >> 3) & 1) * 8 + (lane & 7);   // + mf*16
    int a_ck  = (lane >> 4);                                     // + kk*2
    int b_row = wn * 32 + (lane >> 4) * 8 + (lane & 7);          // + ng*16
    int b_ck  = ((lane >> 3) & 1);                               // + kk*2
    uint32_t sbase = smem_u32(sm);

    for (int ck = 0; ck < 8; ck++) {
        if (ck + 2 < 8) {
            gemm_load_stage(sm, (ck + 2) % 3, ck + 2, tid, a0p, a1p, b0p, b1p);
            CP_WAIT(2);
        } else if (ck + 1 < 8) {
            CP_WAIT(1);
        } else {
            CP_WAIT(0);
        }
        __syncthreads();

        uint32_t st = sbase + (ck % 3) * STG;
        #pragma unroll
        for (int kk = 0; kk < 4; kk++) {
            uint32_t ahi[4][4], alo[4][4];
            #pragma unroll
            for (int mf = 0; mf < 4; mf++) {
                int row = a_row + mf * 16;
                int chv = (kk * 2 + a_ck) ^ (row & 7);
                uint32_t ad = st + row * 128 + (chv << 4);
                LDSM4(ahi[mf], ad);
                LDSM4(alo[mf], ad + 16384);
            }
            uint32_t bhi[2][4], blo[2][4];
            #pragma unroll
            for (int ng = 0; ng < 2; ng++) {
                int row = b_row + ng * 16;
                int chv = (kk * 2 + b_ck) ^ (row & 7);
                uint32_t bd = st + 32768 + row * 128 + (chv << 4);
                LDSM4(bhi[ng], bd);
                LDSM4(blo[ng], bd + 16384);
            }
            #pragma unroll
            for (int mf = 0; mf < 4; mf++)
                #pragma unroll
                for (int ng = 0; ng < 2; ng++)
                    #pragma unroll
                    for (int nh = 0; nh < 2; nh++) {
                        int nf = ng * 2 + nh;
                        MMA16816(acc[mf][nf], ahi[mf], bhi[ng][nh * 2], bhi[ng][nh * 2 + 1]);
                        MMA16816(acc[mf][nf], ahi[mf], blo[ng][nh * 2], blo[ng][nh * 2 + 1]);
                        MMA16816(acc[mf][nf], alo[mf], bhi[ng][nh * 2], bhi[ng][nh * 2 + 1]);
                    }
        }
        __syncthreads();
    }

    // epilogue: direct fragment stores (float2, 8B aligned)
    size_t obase = (size_t)z * M * NPIX;
    #pragma unroll
    for (int mf = 0; mf < 4; mf++) {
        int m = m0 + wm * 64 + mf * 16 + (lane >> 2);
        float bb0 = bias ? bias[m] : 0.f;
        float bb8 = bias ? bias[m + 8] : 0.f;
        #pragma unroll
        for (int nf = 0; nf < 4; nf++) {
            int n = n0 + wn * 32 + nf * 8 + (lane & 3) * 2;
            float2 v0 = make_float2(acc[mf][nf][0] + bb0, acc[mf][nf][1] + bb0);
            float2 v1 = make_float2(acc[mf][nf][2] + bb8, acc[mf][nf][3] + bb8);
            *(float2*)&Cout[obase + (size_t)m * NPIX + n] = v0;
            *(float2*)&Cout[obase + (size_t)(m + 8) * NPIX + n] = v1;
        }
    }
}

// ---------------------------------------------------------------------------
// qlhat: normalized latent queries (batch-invariant). grid=8, 256 threads.
// ---------------------------------------------------------------------------
__global__ __launch_bounds__(256) void qlhat_kernel(
    const float* __restrict__ w_q_lat, const float* __restrict__ latents,
    float* __restrict__ qlhat)
{
    int h = blockIdx.x;
    __shared__ float slat[C][L];
    __shared__ float stile[DH][L];
    __shared__ float snorm[L];
    int tid = threadIdx.x;
    for (int i = tid; i < C * L; i += 256) slat[i >> 4][i & 15] = latents[i];
    __syncthreads();
    for (int p = tid; p < DH * L; p += 256) {
        int j = p >> 4, l = p & 15;
        const float* wrow = w_q_lat + (size_t)(h * DH + j) * C;
        float acc = 0.f;
        for (int c2 = 0; c2 < C; c2++) acc += wrow[c2] * slat[c2][l];
        stile[j][l] = acc;
    }
    __syncthreads();
    if (tid < L) {
        float s = 0.f;
        for (int j = 0; j < DH; j++) { float v = stile[j][tid]; s += v * v; }
        snorm[tid] = 1.f / fmaxf(sqrtf(s), EPSN);
    }
    __syncthreads();
    for (int p = tid; p < DH * L; p += 256)
        qlhat[(h * DH + (p >> 4)) * L + (p & 15)] = stile[p >> 4][p & 15] * snorm[p & 15];
}

// ---------------------------------------------------------------------------
// attn1a: exp(logits) + per-split L-sums. grid (64,4), 256 threads.
// ---------------------------------------------------------------------------
__global__ __launch_bounds__(256) void attn1a_kernel(
    const float* __restrict__ kvx, const float* __restrict__ qlhat,
    float* __restrict__ attn_g, float* __restrict__ lsum_g)
{
    int bh = blockIdx.x, split = blockIdx.y, b = bh >> 3, h = bh & 7;
    const float* kbase = kvx + ((size_t)b * 2 * C + h * DH) * NPIX + split * 1024;
    float* attn = attn_g + (size_t)bh * L * NPIX + split * 1024;

    __shared__ float sql[DH][L];
    __shared__ float wred[8][L];
    int tid = threadIdx.x;
    for (int i = tid; i < DH * L; i += 256)
        sql[i >> 4][i & 15] = qlhat[(h * DH + (i >> 4)) * L + (i & 15)];
    __syncthreads();

    float dot[4][L], nrm[4] = {0.f, 0.f, 0.f, 0.f}, lsum[L];
    #pragma unroll
    for (int l = 0; l < L; l++) lsum[l] = 0.f;
    #pragma unroll
    for (int i = 0; i < 4; i++)
        #pragma unroll
        for (int l = 0; l < L; l++) dot[i][l] = 0.f;

    for (int j = 0; j < DH; j++) {
        const float* kj = kbase + (size_t)j * NPIX + tid;
        float kv[4];
        #pragma unroll
        for (int i = 0; i < 4; i++) { kv[i] = kj[i * 256]; nrm[i] += kv[i] * kv[i]; }
        #pragma unroll
        for (int l = 0; l < L; l++) {
            float s = sql[j][l];
            #pragma unroll
            for (int i = 0; i < 4; i++) dot[i][l] += kv[i] * s;
        }
    }
    #pragma unroll
    for (int i = 0; i < 4; i++) {
        float inv = SCALE / fmaxf(sqrtf(nrm[i]), EPSN);
        #pragma unroll
        for (int l = 0; l < L; l++) {
            float p = __expf(dot[i][l] * inv);
            lsum[l] += p;
            attn[(size_t)l * NPIX + tid + i * 256] = p;
        }
    }
    int lane = tid & 31, wrp = tid >> 5;
    #pragma unroll
    for (int l = 0; l < L; l++) {
        float v = lsum[l];
        #pragma unroll
        for (int o = 16; o; o >>= 1) v += __shfl_xor_sync(0xffffffffu, v, o);
        if (lane == 0) wred[wrp][l] = v;
    }
    __syncthreads();
    if (tid < L) {
        float s = 0.f;
        for (int w = 0; w < 8; w++) s += wred[w][tid];
        lsum_g[bh * 64 + split * 16 + tid] = s;
    }
}

// attn1b: sinv = 1/sum over splits. 1 block, 1024 threads.
__global__ __launch_bounds__(1024) void attn1b_kernel(
    const float* __restrict__ lsum_g, float* __restrict__ sinv_g)
{
    int tid = threadIdx.x;
    int bh = tid >> 4, l = tid & 15;
    float s = 0.f;
    #pragma unroll
    for (int sp = 0; sp < 4; sp++) s += lsum_g[bh * 64 + sp * 16 + l];
    sinv_g[bh * 16 + l] = 1.f / s;
}

// attn1c: partial P@V. grid (64,4), 512 threads.
__global__ __launch_bounds__(512) void attn1c_kernel(
    const float* __restrict__ kvx, const float* __restrict__ attn_g,
    float* __restrict__ latpart)
{
    int bh = blockIdx.x, split = blockIdx.y, b = bh >> 3, h = bh & 7;
    const float* vbase = kvx + ((size_t)b * 2 * C + C + h * DH) * NPIX + split * 1024;
    const float* attn = attn_g + (size_t)bh * L * NPIX + split * 1024;
    int tid = threadIdx.x, lane = tid & 31, wrp = tid >> 5;

    float acc[4][L];
    #pragma unroll
    for (int jj = 0; jj < 4; jj++)
        #pragma unroll
        for (int l = 0; l < L; l++) acc[jj][l] = 0.f;

    for (int it = 0; it < 32; it++) {
        int n = lane + it * 32;
        float pv[L];
        #pragma unroll
        for (int l = 0; l < L; l++) pv[l] = attn[(size_t)l * NPIX + n];
        #pragma unroll
        for (int jj = 0; jj < 4; jj++) {
            float v = vbase[(size_t)(wrp * 4 + jj) * NPIX + n];
            #pragma unroll
            for (int l = 0; l < L; l++) acc[jj][l] += v * pv[l];
        }
    }
    #pragma unroll
    for (int jj = 0; jj < 4; jj++)
        #pragma unroll
        for (int l = 0; l < L; l++) {
            float v = acc[jj][l];
            #pragma unroll
            for (int o = 16; o; o >>= 1) v += __shfl_xor_sync(0xffffffffu, v, o);
            if (lane == 0)
                latpart[split * 65536 + bh * 1024 + (wrp * 4 + jj) * 16 + l] = v;
        }
}

// attn1d: reduce splits + scale by sinv -> latread. grid 256, 256 threads.
__global__ __launch_bounds__(256) void attn1d_kernel(
    const float* __restrict__ latpart, const float* __restrict__ sinv_g,
    float* __restrict__ latread)
{
    int e = blockIdx.x * 256 + threadIdx.x;
    int bh = e >> 10, rem = e & 1023, r = rem >> 4, l = rem & 15;
    float s = latpart[e] + latpart[65536 + e] + latpart[131072 + e] + latpart[196608 + e];
    int b = bh >> 3, h = bh & 7;
    latread[((size_t)b * C + h * DH + r) * L + l] = s * sinv_g[bh * 16 + l];
}

// ---------------------------------------------------------------------------
// kvl: kvl[b] = w_kv_lat @ lat_read[b]; normalize k-part per (head,l).
// ---------------------------------------------------------------------------
__global__ __launch_bounds__(256) void kvl_kernel(
    const float* __restrict__ w_kv_lat, const float* __restrict__ latread,
    float* __restrict__ kvl)
{
    int b = blockIdx.x, c0 = blockIdx.y * 64;
    __shared__ float slat[C][L];
    __shared__ float stile[64][L];
    __shared__ float snorm[L];
    int tid = threadIdx.x;
    const float* lr = latread + (size_t)b * C * L;
    for (int i = tid; i < C * L; i += 256) slat[i >> 4][i & 15] = lr[i];
    __syncthreads();
    for (int p = tid; p < 64 * L; p += 256) {
        int j = p >> 4, l = p & 15;
        const float* wrow = w_kv_lat + (size_t)(c0 + j) * C;
        float acc = 0.f;
        for (int c2 = 0; c2 < C; c2++) acc += wrow[c2] * slat[c2][l];
        stile[j][l] = acc;
    }
    __syncthreads();
    if (c0 < C) {
        if (tid < L) {
            float s = 0.f;
            for (int j = 0; j < 64; j++) { float v = stile[j][tid]; s += v * v; }
            snorm[tid] = 1.f / fmaxf(sqrtf(s), EPSN);
        }
        __syncthreads();
        for (int p = tid; p < 64 * L; p += 256)
            kvl[((size_t)b * 2 * C + c0 + (p >> 4)) * L + (p & 15)] =
                stile[p >> 4][p & 15] * snorm[p & 15];
    } else {
        for (int p = tid; p < 64 * L; p += 256)
            kvl[((size_t)b * 2 * C + c0 + (p >> 4)) * L + (p & 15)] = stile[p >> 4][p & 15];
    }
}

// ---------------------------------------------------------------------------
// attn2: latent write, fused per pixel; writes xwT [b][n][c] bf16 hi/lo.
// grid (32, HEADS, Bsz), 128 threads.
// ---------------------------------------------------------------------------
__global__ __launch_bounds__(128) void attn2_kernel(
    const float* __restrict__ qx, const float* __restrict__ kvl,
    __nv_bfloat16* __restrict__ xwThi, __nv_bfloat16* __restrict__ xwTlo)
{
    int b = blockIdx.z, h = blockIdx.y;
    int tid = threadIdx.x;
    int n = blockIdx.x * 128 + tid;
    __shared__ float skl[DH][L];
    __shared__ float svl[DH][L];
    __shared__ unsigned short sh[DH][128];
    __shared__ unsigned short sl[DH][128];

    const float* kvlb = kvl + (size_t)b * 2 * C * L;
    for (int i = tid; i < DH * L; i += 128) {
        skl[i >> 4][i & 15] = kvlb[(h * DH + (i >> 4)) * L + (i & 15)];
        svl[i >> 4][i & 15] = kvlb[(C + h * DH + (i >> 4)) * L + (i & 15)];
    }
    __syncthreads();

    const float* qcol = qx + ((size_t)b * C + h * DH) * NPIX + n;
    float dot[L], nrm = 0.f;
    #pragma unroll
    for (int l = 0; l < L; l++) dot[l] = 0.f;
    for (int j = 0; j < DH; j++) {
        float q = qcol[(size_t)j * NPIX];
        nrm += q * q;
        #pragma unroll
        for (int l = 0; l < L; l++) dot[l] += q * skl[j][l];
    }
    float inv = SCALE / fmaxf(sqrtf(nrm), EPSN);
    float s = 0.f;
    #pragma unroll
    for (int l = 0; l < L; l++) { dot[l] = __expf(dot[l] * inv); s += dot[l]; }
    float is = 1.f / s;

    for (int j = 0; j < DH; j++) {
        float a = 0.f;
        #pragma unroll
        for (int l = 0; l < L; l++) a += dot[l] * svl[j][l];
        a *= is;
        __nv_bfloat16 hi = __float2bfloat16_rn(a);
        __nv_bfloat16 lo = __float2bfloat16_rn(a - __bfloat162float(hi));
        sh[j][tid] = __bfloat16_as_ushort(hi);
        sl[j][tid] = __bfloat16_as_ushort(lo);
    }
    __syncthreads();

    size_t base = ((size_t)b * NPIX + n) * C + h * DH;
    #pragma unroll
    for (int c4 = 0; c4 < 8; c4++) {
        uint32_t wh[4], wl[4];
        #pragma unroll
        for (int k = 0; k < 4; k++) {
            int j = c4 * 8 + k * 2;
            wh[k] = (uint32_t)sh[j][tid] | ((uint32_t)sh[j + 1][tid] << 16);
            wl[k] = (uint32_t)sl[j][tid] | ((uint32_t)sl[j + 1][tid] << 16);
        }
        *(uint4*)(xwThi + base + c4 * 8) = make_uint4(wh[0], wh[1], wh[2], wh[3]);
        *(uint4*)(xwTlo + base + c4 * 8) = make_uint4(wl[0], wl[1], wl[2], wl[3]);
    }
}

// ---------------------------------------------------------------------------
// Launch
// ---------------------------------------------------------------------------
extern "C" void kernel_launch(void* const* d_in, const int* in_sizes, int n_in,
                              void* d_out, int out_size)
{
    const float* x        = (const float*)d_in[0];
    const float* latents  = (const float*)d_in[1];
    const float* w_q_lat  = (const float*)d_in[2];
    const float* w_kv_x   = (const float*)d_in[3];
    const float* w_q_x    = (const float*)d_in[4];
    const float* w_kv_lat = (const float*)d_in[5];
    const float* w_proj   = (const float*)d_in[6];
    const float* b_proj   = (const float*)d_in[7];
    float* out = (float*)d_out;

    float *kvx, *qx, *attn, *lsum, *sinv, *latpart, *latread, *kvl, *qlhat;
    __nv_bfloat16 *xThi, *xTlo, *xwThi, *xwTlo;
    __nv_bfloat16 *wkvhi, *wkvlo, *wqhi, *wqlo, *wphi, *wplo;
    cudaGetSymbolAddress((void**)&kvx, g_kvx);
    cudaGetSymbolAddress((void**)&qx, g_qx);
    cudaGetSymbolAddress((void**)&attn, g_attn);
    cudaGetSymbolAddress((void**)&lsum, g_lsum);
    cudaGetSymbolAddress((void**)&sinv, g_sinv);
    cudaGetSymbolAddress((void**)&latpart, g_latpart);
    cudaGetSymbolAddress((void**)&latread, g_latread);
    cudaGetSymbolAddress((void**)&kvl, g_kvl);
    cudaGetSymbolAddress((void**)&qlhat, g_qlhat);
    cudaGetSymbolAddress((void**)&xThi, g_xThi);
    cudaGetSymbolAddress((void**)&xTlo, g_xTlo);
    cudaGetSymbolAddress((void**)&xwThi, g_xwThi);
    cudaGetSymbolAddress((void**)&xwTlo, g_xwTlo);
    cudaGetSymbolAddress((void**)&wkvhi, g_wkvhi);
    cudaGetSymbolAddress((void**)&wkvlo, g_wkvlo);
    cudaGetSymbolAddress((void**)&wqhi, g_wqhi);
    cudaGetSymbolAddress((void**)&wqlo, g_wqlo);
    cudaGetSymbolAddress((void**)&wphi, g_wphi);
    cudaGetSymbolAddress((void**)&wplo, g_wplo);

    cudaFuncSetAttribute(gemm_mma, cudaFuncAttributeMaxDynamicSharedMemorySize, 3 * STG);

    // operand preparation
    wsplit_kernel<<<(2 * C * KDIM) / 1024, 256>>>(w_kv_x, wkvhi, wkvlo, (2 * C * KDIM) / 4);
    wsplit_kernel<<<(C * KDIM) / 1024, 256>>>(w_q_x, wqhi, wqlo, (C * KDIM) / 4);
    wsplit_kernel<<<(C * KDIM) / 1024, 256>>>(w_proj, wphi, wplo, (C * KDIM) / 4);
    tsplit_kernel<<<dim3(NPIX / 32, C / 32, Bsz), dim3(32, 8)>>>(x, xThi, xTlo);
    qlhat_kernel<<<HEADS, 256>>>(w_q_lat, latents, qlhat);

    // big GEMMs on tensor pipe (HMMA)
    gemm_mma<<<dim3(32, 8, Bsz), 256, 3 * STG>>>(wkvhi, wkvlo, xThi, xTlo, kvx, nullptr, 1024);
    gemm_mma<<<dim3(32, 4, Bsz), 256, 3 * STG>>>(wqhi, wqlo, xThi, xTlo, qx, nullptr, 512);

    // latent read attention
    attn1a_kernel<<<dim3(64, 4), 256>>>(kvx, qlhat, attn, lsum);
    attn1b_kernel<<<1, 1024>>>(lsum, sinv);
    attn1c_kernel<<<dim3(64, 4), 512>>>(kvx, attn, latpart);
    attn1d_kernel<<<256, 256>>>(latpart, sinv, latread);

    kvl_kernel<<<dim3(Bsz, 16), 256>>>(w_kv_lat, latread, kvl);

    // latent write attention -> bf16 hi/lo transposed
    attn2_kernel<<<dim3(32, HEADS, Bsz), 128>>>(qx, kvl, xwThi, xwTlo);

    // output projection + bias
    gemm_mma<<<dim3(32, 4, Bsz), 256, 3 * STG>>>(wphi, wplo, xwThi, xwTlo, out, b_proj, 512);
}

// round 5
// speedup vs baseline: 2.7550x; 1.2050x over previous
#include <cuda_runtime.h>
#include <cuda_fp16.h>
#include <math.h>
#include <stdint.h>

// ---------------------------------------------------------------------------
// LatentMixer on GB300 (sm_103 plain target): HMMA fp16 2-term split GEMMs
// + fused attention. B=8, C=512, N=4096, heads=8, d=64, L=16, scale=0.125
// Split scheme: weights single fp16; x split into fp16 hi+lo.
//   w*x ~= w*x_hi + w*x_lo  (error = weight rounding ~2^-11 rel)
// ---------------------------------------------------------------------------

#define Bsz 8
#define C   512
#define NPIX 4096
#define L   16
#define HEADS 8
#define DH  64
#define SCALE 0.125f
#define EPSN 1e-12f
#define KDIM 512
#define MROWS 1536   // stacked kv(1024) + q(512)

// ---------------- scratch (device globals; allocation-free contract) -------
__device__ float g_kvq[(size_t)Bsz * MROWS * NPIX];   // rows: [0,512)k [512,1024)v [1024,1536)q
__device__ float g_attn[(size_t)Bsz * HEADS * L * NPIX];
__device__ float g_lsum[64 * 4 * L];
__device__ float g_sinv[64 * L];
__device__ float g_latpart[4 * 64 * DH * L];
__device__ float g_latread[Bsz * C * L];
__device__ float g_kvl[Bsz * 2 * C * L];
__device__ float g_qlhat[C * L];
__device__ __half g_xThi[(size_t)Bsz * NPIX * C];
__device__ __half g_xTlo[(size_t)Bsz * NPIX * C];
__device__ __half g_xwThi[(size_t)Bsz * NPIX * C];
__device__ __half g_xwTlo[(size_t)Bsz * NPIX * C];
__device__ __half g_wA[MROWS * KDIM];     // stacked w_kv_x ; w_q_x (fp16)
__device__ __half g_wp[C * KDIM];         // w_proj (fp16)

// ---------------- helpers ---------------------------------------------------
__device__ __forceinline__ uint32_t smem_u32(const void* p) {
    uint32_t a;
    asm("{ .reg .u64 t; cvta.to.shared.u64 t, %1; cvt.u32.u64 %0, t; }" : "=r"(a) : "l"(p));
    return a;
}

#define LDSM4(r, addr) \
    asm volatile("ldmatrix.sync.aligned.m8n8.x4.shared.b16 {%0,%1,%2,%3}, [%4];" \
                 : "=r"((r)[0]), "=r"((r)[1]), "=r"((r)[2]), "=r"((r)[3]) : "r"(addr))

#define MMA16816(cc, aa, b0, b1) \
    asm volatile("mma.sync.aligned.m16n8k16.row.col.f32.f16.f16.f32 " \
                 "{%0,%1,%2,%3}, {%4,%5,%6,%7}, {%8,%9}, {%0,%1,%2,%3};" \
                 : "+f"((cc)[0]), "+f"((cc)[1]), "+f"((cc)[2]), "+f"((cc)[3]) \
                 : "r"((aa)[0]), "r"((aa)[1]), "r"((aa)[2]), "r"((aa)[3]), \
                   "r"(b0), "r"(b1))

#define CP_ASYNC16(dst, src) \
    asm volatile("cp.async.cg.shared.global [%0], [%1], 16;" :: "r"(dst), "l"(src))
#define CP_COMMIT() asm volatile("cp.async.commit_group;" ::: "memory")
#define CP_WAIT(n)  asm volatile("cp.async.wait_group %0;" :: "n"(n) : "memory")

// ---------------------------------------------------------------------------
// Weight convert: fp32 -> single fp16
// ---------------------------------------------------------------------------
__global__ __launch_bounds__(256) void wconv_kernel(
    const float* __restrict__ a, __half* __restrict__ hi, int n4)
{
    int i = blockIdx.x * 256 + threadIdx.x;
    if (i >= n4) return;
    float4 v = ((const float4*)a)[i];
    __half2* o = (__half2*)(hi + i * 4);
    o[0] = __floats2half2_rn(v.x, v.y);
    o[1] = __floats2half2_rn(v.z, v.w);
}

// ---------------------------------------------------------------------------
// Transpose + split x: [B,C,N] fp32 -> [B,N,C] fp16 hi/lo. 32x32 tiles.
// ---------------------------------------------------------------------------
__global__ __launch_bounds__(256) void tsplit_kernel(
    const float* __restrict__ x, __half* __restrict__ hi,
    __half* __restrict__ lo)
{
    __shared__ float t[32][33];
    int n0 = blockIdx.x * 32, c0 = blockIdx.y * 32, b = blockIdx.z;
    int tx = threadIdx.x, ty = threadIdx.y;
    const float* xb = x + (size_t)b * C * NPIX;
    #pragma unroll
    for (int i = 0; i < 4; i++)
        t[ty + i * 8][tx] = xb[(size_t)(c0 + ty + i * 8) * NPIX + n0 + tx];
    __syncthreads();
    __half* hb = hi + (size_t)b * NPIX * C;
    __half* lb = lo + (size_t)b * NPIX * C;
    #pragma unroll
    for (int i = 0; i < 4; i++) {
        float v = t[tx][ty + i * 8];
        __half h = __float2half_rn(v);
        size_t o = (size_t)(n0 + ty + i * 8) * C + c0 + tx;
        hb[o] = h;
        lb[o] = __float2half_rn(v - __half2float(h));
    }
}

// ---------------------------------------------------------------------------
// HMMA GEMM: Cout[z][m][n] = sum_k A[m][k]*(Bhi+Blo)[z][n][k], fp16 2-term.
// A: [M,512] fp16 K-major; Bhi/Blo: [B,4096,512] fp16 K-major.
// Tile 128x128x64, 256 threads (2x4 warps, warp tile 64x32), 3-stage cp.async.
// smem stage: A(16K) Bhi(16K) Blo(16K) = 48K, SW128 swizzle.
// ---------------------------------------------------------------------------
#define STG 49152
__device__ __forceinline__ void gemm_load_stage(
    char* sm, int stg, int ck, int tid,
    const __half* a0, const __half* b0, const __half* b1)
{
    char* d = sm + stg * STG;
    #pragma unroll
    for (int i = 0; i < 12; i++) {
        int u = tid + i * 256;
        int r = u >> 10, idx = u & 1023, row = idx >> 3, c = idx & 7;
        const __half* src =
            ((r == 0) ? a0 : (r == 1) ? b0 : b1)
            + (size_t)row * KDIM + ck * 64 + c * 8;
        uint32_t dst = smem_u32(d + r * 16384 + row * 128 + (((c ^ (row & 7))) << 4));
        CP_ASYNC16(dst, src);
    }
    CP_COMMIT();
}

__global__ __launch_bounds__(256) void gemm_mma(
    const __half* __restrict__ A,
    const __half* __restrict__ Bhi, const __half* __restrict__ Blo,
    float* __restrict__ Cout, const float* __restrict__ bias, int M)
{
    extern __shared__ char sm[];
    int tid = threadIdx.x, lane = tid & 31, wid = tid >> 5;
    int wm = wid >> 2, wn = wid & 3;            // 2 x 4 warps
    int m0 = blockIdx.y * 128, n0 = blockIdx.x * 128, z = blockIdx.z;

    const __half* a0p = A + (size_t)m0 * KDIM;
    const __half* b0p = Bhi + ((size_t)z * NPIX + n0) * KDIM;
    const __half* b1p = Blo + ((size_t)z * NPIX + n0) * KDIM;

    float acc[4][4][4];
    #pragma unroll
    for (int i = 0; i < 4; i++)
        #pragma unroll
        for (int j = 0; j < 4; j++)
            #pragma unroll
            for (int k = 0; k < 4; k++) acc[i][j][k] = 0.f;

    gemm_load_stage(sm, 0, 0, tid, a0p, b0p, b1p);
    gemm_load_stage(sm, 1, 1, tid, a0p, b0p, b1p);

    int a_row = wm * 64 + ((lane >> 3) & 1) * 8 + (lane & 7);   // + mf*16
    int a_ck  = (lane >> 4);                                     // + kk*2
    int b_row = wn * 32 + (lane >> 4) * 8 + (lane & 7);          // + ng*16
    int b_ck  = ((lane >> 3) & 1);                               // + kk*2
    uint32_t sbase = smem_u32(sm);

    for (int ck = 0; ck < 8; ck++) {
        if (ck + 2 < 8) {
            gemm_load_stage(sm, (ck + 2) % 3, ck + 2, tid, a0p, b0p, b1p);
            CP_WAIT(2);
        } else if (ck + 1 < 8) {
            CP_WAIT(1);
        } else {
            CP_WAIT(0);
        }
        __syncthreads();

        uint32_t st = sbase + (ck % 3) * STG;
        #pragma unroll
        for (int kk = 0; kk < 4; kk++) {
            uint32_t af[4][4];
            #pragma unroll
            for (int mf = 0; mf < 4; mf++) {
                int row = a_row + mf * 16;
                int chv = (kk * 2 + a_ck) ^ (row & 7);
                LDSM4(af[mf], st + row * 128 + (chv << 4));
            }
            uint32_t bhi[2][4], blo[2][4];
            #pragma unroll
            for (int ng = 0; ng < 2; ng++) {
                int row = b_row + ng * 16;
                int chv = (kk * 2 + b_ck) ^ (row & 7);
                uint32_t bd = st + 16384 + row * 128 + (chv << 4);
                LDSM4(bhi[ng], bd);
                LDSM4(blo[ng], bd + 16384);
            }
            #pragma unroll
            for (int mf = 0; mf < 4; mf++)
                #pragma unroll
                for (int ng = 0; ng < 2; ng++)
                    #pragma unroll
                    for (int nh = 0; nh < 2; nh++) {
                        int nf = ng * 2 + nh;
                        MMA16816(acc[mf][nf], af[mf], bhi[ng][nh * 2], bhi[ng][nh * 2 + 1]);
                        MMA16816(acc[mf][nf], af[mf], blo[ng][nh * 2], blo[ng][nh * 2 + 1]);
                    }
        }
        __syncthreads();
    }

    // epilogue: direct fragment stores (float2, 8B aligned)
    size_t obase = (size_t)z * M * NPIX;
    #pragma unroll
    for (int mf = 0; mf < 4; mf++) {
        int m = m0 + wm * 64 + mf * 16 + (lane >> 2);
        float bb0 = bias ? bias[m] : 0.f;
        float bb8 = bias ? bias[m + 8] : 0.f;
        #pragma unroll
        for (int nf = 0; nf < 4; nf++) {
            int n = n0 + wn * 32 + nf * 8 + (lane & 3) * 2;
            float2 v0 = make_float2(acc[mf][nf][0] + bb0, acc[mf][nf][1] + bb0);
            float2 v1 = make_float2(acc[mf][nf][2] + bb8, acc[mf][nf][3] + bb8);
            *(float2*)&Cout[obase + (size_t)m * NPIX + n] = v0;
            *(float2*)&Cout[obase + (size_t)(m + 8) * NPIX + n] = v1;
        }
    }
}

// ---------------------------------------------------------------------------
// qlhat: normalized latent queries (batch-invariant). grid=8, 256 threads.
// ---------------------------------------------------------------------------
__global__ __launch_bounds__(256) void qlhat_kernel(
    const float* __restrict__ w_q_lat, const float* __restrict__ latents,
    float* __restrict__ qlhat)
{
    int h = blockIdx.x;
    __shared__ float slat[C][L];
    __shared__ float stile[DH][L];
    __shared__ float snorm[L];
    int tid = threadIdx.x;
    for (int i = tid; i < C * L; i += 256) slat[i >> 4][i & 15] = latents[i];
    __syncthreads();
    for (int p = tid; p < DH * L; p += 256) {
        int j = p >> 4, l = p & 15;
        const float* wrow = w_q_lat + (size_t)(h * DH + j) * C;
        float acc = 0.f;
        for (int c2 = 0; c2 < C; c2++) acc += wrow[c2] * slat[c2][l];
        stile[j][l] = acc;
    }
    __syncthreads();
    if (tid < L) {
        float s = 0.f;
        for (int j = 0; j < DH; j++) { float v = stile[j][tid]; s += v * v; }
        snorm[tid] = 1.f / fmaxf(sqrtf(s), EPSN);
    }
    __syncthreads();
    for (int p = tid; p < DH * L; p += 256)
        qlhat[(h * DH + (p >> 4)) * L + (p & 15)] = stile[p >> 4][p & 15] * snorm[p & 15];
}

// ---------------------------------------------------------------------------
// attn1a: exp(logits) + per-split L-sums. grid (64,4), 256 threads.
// ---------------------------------------------------------------------------
__global__ __launch_bounds__(256) void attn1a_kernel(
    const float* __restrict__ kvq, const float* __restrict__ qlhat,
    float* __restrict__ attn_g, float* __restrict__ lsum_g)
{
    int bh = blockIdx.x, split = blockIdx.y, b = bh >> 3, h = bh & 7;
    const float* kbase = kvq + ((size_t)b * MROWS + h * DH) * NPIX + split * 1024;
    float* attn = attn_g + (size_t)bh * L * NPIX + split * 1024;

    __shared__ float sql[DH][L];
    __shared__ float wred[8][L];
    int tid = threadIdx.x;
    for (int i = tid; i < DH * L; i += 256)
        sql[i >> 4][i & 15] = qlhat[(h * DH + (i >> 4)) * L + (i & 15)];
    __syncthreads();

    float dot[4][L], nrm[4] = {0.f, 0.f, 0.f, 0.f}, lsum[L];
    #pragma unroll
    for (int l = 0; l < L; l++) lsum[l] = 0.f;
    #pragma unroll
    for (int i = 0; i < 4; i++)
        #pragma unroll
        for (int l = 0; l < L; l++) dot[i][l] = 0.f;

    for (int j = 0; j < DH; j++) {
        const float* kj = kbase + (size_t)j * NPIX + tid;
        float kv[4];
        #pragma unroll
        for (int i = 0; i < 4; i++) { kv[i] = kj[i * 256]; nrm[i] += kv[i] * kv[i]; }
        #pragma unroll
        for (int l = 0; l < L; l++) {
            float s = sql[j][l];
            #pragma unroll
            for (int i = 0; i < 4; i++) dot[i][l] += kv[i] * s;
        }
    }
    #pragma unroll
    for (int i = 0; i < 4; i++) {
        float inv = SCALE / fmaxf(sqrtf(nrm[i]), EPSN);
        #pragma unroll
        for (int l = 0; l < L; l++) {
            float p = __expf(dot[i][l] * inv);
            lsum[l] += p;
            attn[(size_t)l * NPIX + tid + i * 256] = p;
        }
    }
    int lane = tid & 31, wrp = tid >> 5;
    #pragma unroll
    for (int l = 0; l < L; l++) {
        float v = lsum[l];
        #pragma unroll
        for (int o = 16; o; o >>= 1) v += __shfl_xor_sync(0xffffffffu, v, o);
        if (lane == 0) wred[wrp][l] = v;
    }
    __syncthreads();
    if (tid < L) {
        float s = 0.f;
        for (int w = 0; w < 8; w++) s += wred[w][tid];
        lsum_g[bh * 64 + split * 16 + tid] = s;
    }
}

// attn1b: sinv = 1/sum over splits. 1 block, 1024 threads.
__global__ __launch_bounds__(1024) void attn1b_kernel(
    const float* __restrict__ lsum_g, float* __restrict__ sinv_g)
{
    int tid = threadIdx.x;
    int bh = tid >> 4, l = tid & 15;
    float s = 0.f;
    #pragma unroll
    for (int sp = 0; sp < 4; sp++) s += lsum_g[bh * 64 + sp * 16 + l];
    sinv_g[bh * 16 + l] = 1.f / s;
}

// attn1c: partial P@V. grid (64,4), 512 threads.
__global__ __launch_bounds__(512) void attn1c_kernel(
    const float* __restrict__ kvq, const float* __restrict__ attn_g,
    float* __restrict__ latpart)
{
    int bh = blockIdx.x, split = blockIdx.y, b = bh >> 3, h = bh & 7;
    const float* vbase = kvq + ((size_t)b * MROWS + 512 + h * DH) * NPIX + split * 1024;
    const float* attn = attn_g + (size_t)bh * L * NPIX + split * 1024;
    int tid = threadIdx.x, lane = tid & 31, wrp = tid >> 5;

    float acc[4][L];
    #pragma unroll
    for (int jj = 0; jj < 4; jj++)
        #pragma unroll
        for (int l = 0; l < L; l++) acc[jj][l] = 0.f;

    for (int it = 0; it < 32; it++) {
        int n = lane + it * 32;
        float pv[L];
        #pragma unroll
        for (int l = 0; l < L; l++) pv[l] = attn[(size_t)l * NPIX + n];
        #pragma unroll
        for (int jj = 0; jj < 4; jj++) {
            float v = vbase[(size_t)(wrp * 4 + jj) * NPIX + n];
            #pragma unroll
            for (int l = 0; l < L; l++) acc[jj][l] += v * pv[l];
        }
    }
    #pragma unroll
    for (int jj = 0; jj < 4; jj++)
        #pragma unroll
        for (int l = 0; l < L; l++) {
            float v = acc[jj][l];
            #pragma unroll
            for (int o = 16; o; o >>= 1) v += __shfl_xor_sync(0xffffffffu, v, o);
            if (lane == 0)
                latpart[split * 65536 + bh * 1024 + (wrp * 4 + jj) * 16 + l] = v;
        }
}

// attn1d: reduce splits + scale by sinv -> latread. grid 256, 256 threads.
__global__ __launch_bounds__(256) void attn1d_kernel(
    const float* __restrict__ latpart, const float* __restrict__ sinv_g,
    float* __restrict__ latread)
{
    int e = blockIdx.x * 256 + threadIdx.x;
    int bh = e >> 10, rem = e & 1023, r = rem >> 4, l = rem & 15;
    float s = latpart[e] + latpart[65536 + e] + latpart[131072 + e] + latpart[196608 + e];
    int b = bh >> 3, h = bh & 7;
    latread[((size_t)b * C + h * DH + r) * L + l] = s * sinv_g[bh * 16 + l];
}

// ---------------------------------------------------------------------------
// kvl: kvl[b] = w_kv_lat @ lat_read[b]; normalize k-part per (head,l).
// ---------------------------------------------------------------------------
__global__ __launch_bounds__(256) void kvl_kernel(
    const float* __restrict__ w_kv_lat, const float* __restrict__ latread,
    float* __restrict__ kvl)
{
    int b = blockIdx.x, c0 = blockIdx.y * 64;
    __shared__ float slat[C][L];
    __shared__ float stile[64][L];
    __shared__ float snorm[L];
    int tid = threadIdx.x;
    const float* lr = latread + (size_t)b * C * L;
    for (int i = tid; i < C * L; i += 256) slat[i >> 4][i & 15] = lr[i];
    __syncthreads();
    for (int p = tid; p < 64 * L; p += 256) {
        int j = p >> 4, l = p & 15;
        const float* wrow = w_kv_lat + (size_t)(c0 + j) * C;
        float acc = 0.f;
        for (int c2 = 0; c2 < C; c2++) acc += wrow[c2] * slat[c2][l];
        stile[j][l] = acc;
    }
    __syncthreads();
    if (c0 < C) {
        if (tid < L) {
            float s = 0.f;
            for (int j = 0; j < 64; j++) { float v = stile[j][tid]; s += v * v; }
            snorm[tid] = 1.f / fmaxf(sqrtf(s), EPSN);
        }
        __syncthreads();
        for (int p = tid; p < 64 * L; p += 256)
            kvl[((size_t)b * 2 * C + c0 + (p >> 4)) * L + (p & 15)] =
                stile[p >> 4][p & 15] * snorm[p & 15];
    } else {
        for (int p = tid; p < 64 * L; p += 256)
            kvl[((size_t)b * 2 * C + c0 + (p >> 4)) * L + (p & 15)] = stile[p >> 4][p & 15];
    }
}

// ---------------------------------------------------------------------------
// attn2: latent write, fused per pixel; writes xwT [b][n][c] fp16 hi/lo.
// grid (32, HEADS, Bsz), 128 threads.
// ---------------------------------------------------------------------------
__global__ __launch_bounds__(128) void attn2_kernel(
    const float* __restrict__ kvq, const float* __restrict__ kvl,
    __half* __restrict__ xwThi, __half* __restrict__ xwTlo)
{
    int b = blockIdx.z, h = blockIdx.y;
    int tid = threadIdx.x;
    int n = blockIdx.x * 128 + tid;
    __shared__ float skl[DH][L];
    __shared__ float svl[DH][L];
    __shared__ unsigned short sh[DH][128];
    __shared__ unsigned short sl[DH][128];

    const float* kvlb = kvl + (size_t)b * 2 * C * L;
    for (int i = tid; i < DH * L; i += 128) {
        skl[i >> 4][i & 15] = kvlb[(h * DH + (i >> 4)) * L + (i & 15)];
        svl[i >> 4][i & 15] = kvlb[(C + h * DH + (i >> 4)) * L + (i & 15)];
    }
    __syncthreads();

    const float* qcol = kvq + ((size_t)b * MROWS + 1024 + h * DH) * NPIX + n;
    float dot[L], nrm = 0.f;
    #pragma unroll
    for (int l = 0; l < L; l++) dot[l] = 0.f;
    for (int j = 0; j < DH; j++) {
        float q = qcol[(size_t)j * NPIX];
        nrm += q * q;
        #pragma unroll
        for (int l = 0; l < L; l++) dot[l] += q * skl[j][l];
    }
    float inv = SCALE / fmaxf(sqrtf(nrm), EPSN);
    float s = 0.f;
    #pragma unroll
    for (int l = 0; l < L; l++) { dot[l] = __expf(dot[l] * inv); s += dot[l]; }
    float is = 1.f / s;

    for (int j = 0; j < DH; j++) {
        float a = 0.f;
        #pragma unroll
        for (int l = 0; l < L; l++) a += dot[l] * svl[j][l];
        a *= is;
        __half hi = __float2half_rn(a);
        __half lo = __float2half_rn(a - __half2float(hi));
        sh[j][tid] = __half_as_ushort(hi);
        sl[j][tid] = __half_as_ushort(lo);
    }
    __syncthreads();

    size_t base = ((size_t)b * NPIX + n) * C + h * DH;
    #pragma unroll
    for (int c4 = 0; c4 < 8; c4++) {
        uint32_t wh[4], wl[4];
        #pragma unroll
        for (int k = 0; k < 4; k++) {
            int j = c4 * 8 + k * 2;
            wh[k] = (uint32_t)sh[j][tid] | ((uint32_t)sh[j + 1][tid] << 16);
            wl[k] = (uint32_t)sl[j][tid] | ((uint32_t)sl[j + 1][tid] << 16);
        }
        *(uint4*)(xwThi + base + c4 * 8) = make_uint4(wh[0], wh[1], wh[2], wh[3]);
        *(uint4*)(xwTlo + base + c4 * 8) = make_uint4(wl[0], wl[1], wl[2], wl[3]);
    }
}

// ---------------------------------------------------------------------------
// Launch
// ---------------------------------------------------------------------------
extern "C" void kernel_launch(void* const* d_in, const int* in_sizes, int n_in,
                              void* d_out, int out_size)
{
    const float* x        = (const float*)d_in[0];
    const float* latents  = (const float*)d_in[1];
    const float* w_q_lat  = (const float*)d_in[2];
    const float* w_kv_x   = (const float*)d_in[3];
    const float* w_q_x    = (const float*)d_in[4];
    const float* w_kv_lat = (const float*)d_in[5];
    const float* w_proj   = (const float*)d_in[6];
    const float* b_proj   = (const float*)d_in[7];
    float* out = (float*)d_out;

    float *kvq, *attn, *lsum, *sinv, *latpart, *latread, *kvl, *qlhat;
    __half *xThi, *xTlo, *xwThi, *xwTlo, *wA, *wp;
    cudaGetSymbolAddress((void**)&kvq, g_kvq);
    cudaGetSymbolAddress((void**)&attn, g_attn);
    cudaGetSymbolAddress((void**)&lsum, g_lsum);
    cudaGetSymbolAddress((void**)&sinv, g_sinv);
    cudaGetSymbolAddress((void**)&latpart, g_latpart);
    cudaGetSymbolAddress((void**)&latread, g_latread);
    cudaGetSymbolAddress((void**)&kvl, g_kvl);
    cudaGetSymbolAddress((void**)&qlhat, g_qlhat);
    cudaGetSymbolAddress((void**)&xThi, g_xThi);
    cudaGetSymbolAddress((void**)&xTlo, g_xTlo);
    cudaGetSymbolAddress((void**)&xwThi, g_xwThi);
    cudaGetSymbolAddress((void**)&xwTlo, g_xwTlo);
    cudaGetSymbolAddress((void**)&wA, g_wA);
    cudaGetSymbolAddress((void**)&wp, g_wp);

    cudaFuncSetAttribute(gemm_mma, cudaFuncAttributeMaxDynamicSharedMemorySize, 3 * STG);

    // operand preparation: stacked weights [kv ; q] fp16, proj fp16, xT split
    wconv_kernel<<<(2 * C * KDIM / 4 + 255) / 256, 256>>>(w_kv_x, wA, 2 * C * KDIM / 4);
    wconv_kernel<<<(C * KDIM / 4 + 255) / 256, 256>>>(w_q_x, wA + 2 * C * KDIM, C * KDIM / 4);
    wconv_kernel<<<(C * KDIM / 4 + 255) / 256, 256>>>(w_proj, wp, C * KDIM / 4);
    tsplit_kernel<<<dim3(NPIX / 32, C / 32, Bsz), dim3(32, 8)>>>(x, xThi, xTlo);
    qlhat_kernel<<<HEADS, 256>>>(w_q_lat, latents, qlhat);

    // fused kv+q GEMM (M=1536) on tensor pipe
    gemm_mma<<<dim3(32, 12, Bsz), 256, 3 * STG>>>(wA, xThi, xTlo, kvq, nullptr, MROWS);

    // latent read attention
    attn1a_kernel<<<dim3(64, 4), 256>>>(kvq, qlhat, attn, lsum);
    attn1b_kernel<<<1, 1024>>>(lsum, sinv);
    attn1c_kernel<<<dim3(64, 4), 512>>>(kvq, attn, latpart);
    attn1d_kernel<<<256, 256>>>(latpart, sinv, latread);

    kvl_kernel<<<dim3(Bsz, 16), 256>>>(w_kv_lat, latread, kvl);

    // latent write attention -> fp16 hi/lo transposed
    attn2_kernel<<<dim3(32, HEADS, Bsz), 128>>>(kvq, kvl, xwThi, xwTlo);

    // output projection + bias
    gemm_mma<<<dim3(32, 4, Bsz), 256, 3 * STG>>>(wp, xwThi, xwTlo, out, b_proj, 512);
}

// round 6
// speedup vs baseline: 4.1338x; 1.5005x over previous
#include <cuda_runtime.h>
#include <cuda_fp16.h>
#include <math.h>
#include <stdint.h>

// ---------------------------------------------------------------------------
// LatentMixer on GB300 (sm_103 plain target): single-term fp16 HMMA GEMMs
// (mma.sync rt=16 roofline-bound -> minimize MMA count) + fused attention.
// B=8, C=512, N=4096, heads=8, d=64, L=16, scale=0.125
// ---------------------------------------------------------------------------

#define Bsz 8
#define C   512
#define NPIX 4096
#define L   16
#define HEADS 8
#define DH  64
#define SCALE 0.125f
#define EPSN 1e-12f
#define KDIM 512
#define MROWS 1536   // stacked k(512) v(512) q(512)

// ---------------- scratch (device globals; allocation-free contract) -------
__device__ __half g_kvq[(size_t)Bsz * MROWS * NPIX];   // fp16 k/v/q
__device__ float g_attn[(size_t)Bsz * HEADS * L * NPIX];
__device__ float g_lsum[64 * 4 * L];
__device__ float g_sinv[64 * L];
__device__ float g_latpart[4 * 64 * DH * L];
__device__ float g_latread[Bsz * C * L];
__device__ float g_kvl[Bsz * 2 * C * L];
__device__ float g_qlhat[C * L];
__device__ __half g_xT [(size_t)Bsz * NPIX * C];       // x transposed fp16
__device__ __half g_xwT[(size_t)Bsz * NPIX * C];       // attn2 out fp16
__device__ __half g_wA[MROWS * KDIM];                  // stacked w_kv_x ; w_q_x
__device__ __half g_wp[C * KDIM];                      // w_proj

// ---------------- helpers ---------------------------------------------------
__device__ __forceinline__ uint32_t smem_u32(const void* p) {
    uint32_t a;
    asm("{ .reg .u64 t; cvta.to.shared.u64 t, %1; cvt.u32.u64 %0, t; }" : "=r"(a) : "l"(p));
    return a;
}

#define LDSM4(r, addr) \
    asm volatile("ldmatrix.sync.aligned.m8n8.x4.shared.b16 {%0,%1,%2,%3}, [%4];" \
                 : "=r"((r)[0]), "=r"((r)[1]), "=r"((r)[2]), "=r"((r)[3]) : "r"(addr))

#define MMA16816(cc, aa, b0, b1) \
    asm volatile("mma.sync.aligned.m16n8k16.row.col.f32.f16.f16.f32 " \
                 "{%0,%1,%2,%3}, {%4,%5,%6,%7}, {%8,%9}, {%0,%1,%2,%3};" \
                 : "+f"((cc)[0]), "+f"((cc)[1]), "+f"((cc)[2]), "+f"((cc)[3]) \
                 : "r"((aa)[0]), "r"((aa)[1]), "r"((aa)[2]), "r"((aa)[3]), \
                   "r"(b0), "r"(b1))

#define CP_ASYNC16(dst, src) \
    asm volatile("cp.async.cg.shared.global [%0], [%1], 16;" :: "r"(dst), "l"(src))
#define CP_COMMIT() asm volatile("cp.async.commit_group;" ::: "memory")
#define CP_WAIT(n)  asm volatile("cp.async.wait_group %0;" :: "n"(n) : "memory")

// ---------------------------------------------------------------------------
// Weight convert: fp32 -> fp16
// ---------------------------------------------------------------------------
__global__ __launch_bounds__(256) void wconv_kernel(
    const float* __restrict__ a, __half* __restrict__ hi, int n4)
{
    int i = blockIdx.x * 256 + threadIdx.x;
    if (i >= n4) return;
    float4 v = ((const float4*)a)[i];
    __half2* o = (__half2*)(hi + i * 4);
    o[0] = __floats2half2_rn(v.x, v.y);
    o[1] = __floats2half2_rn(v.z, v.w);
}

// ---------------------------------------------------------------------------
// Transpose x: [B,C,N] fp32 -> [B,N,C] fp16. 32x32 tiles.
// ---------------------------------------------------------------------------
__global__ __launch_bounds__(256) void tconv_kernel(
    const float* __restrict__ x, __half* __restrict__ xo)
{
    __shared__ float t[32][33];
    int n0 = blockIdx.x * 32, c0 = blockIdx.y * 32, b = blockIdx.z;
    int tx = threadIdx.x, ty = threadIdx.y;
    const float* xb = x + (size_t)b * C * NPIX;
    #pragma unroll
    for (int i = 0; i < 4; i++)
        t[ty + i * 8][tx] = xb[(size_t)(c0 + ty + i * 8) * NPIX + n0 + tx];
    __syncthreads();
    __half* ob = xo + (size_t)b * NPIX * C;
    #pragma unroll
    for (int i = 0; i < 4; i++)
        ob[(size_t)(n0 + ty + i * 8) * C + c0 + tx] = __float2half_rn(t[tx][ty + i * 8]);
}

// ---------------------------------------------------------------------------
// HMMA GEMM: C[z][m][n] = sum_k A[m][k]*B[z][n][k], single fp16 term.
// Tile 128x128x64, 256 threads (2x4 warps, warp tile 64x32), 3-stage cp.async.
// smem stage: A(16K) B(16K) = 32K, SW128-style xor swizzle.
// Output: fp16 (Ch) or fp32+bias (Cf).
// ---------------------------------------------------------------------------
#define STG 32768
__device__ __forceinline__ void gemm_load_stage(
    char* sm, int stg, int ck, int tid,
    const __half* a0, const __half* b0)
{
    char* d = sm + stg * STG;
    #pragma unroll
    for (int i = 0; i < 8; i++) {
        int u = tid + i * 256;
        int r = u >> 10, idx = u & 1023, row = idx >> 3, c = idx & 7;
        const __half* src = ((r == 0) ? a0 : b0) + (size_t)row * KDIM + ck * 64 + c * 8;
        uint32_t dst = smem_u32(d + r * 16384 + row * 128 + (((c ^ (row & 7))) << 4));
        CP_ASYNC16(dst, src);
    }
    CP_COMMIT();
}

__global__ __launch_bounds__(256) void gemm_mma(
    const __half* __restrict__ A, const __half* __restrict__ B,
    __half* __restrict__ Ch, float* __restrict__ Cf,
    const float* __restrict__ bias, int M)
{
    extern __shared__ char sm[];
    int tid = threadIdx.x, lane = tid & 31, wid = tid >> 5;
    int wm = wid >> 2, wn = wid & 3;
    int m0 = blockIdx.y * 128, n0 = blockIdx.x * 128, z = blockIdx.z;

    const __half* a0p = A + (size_t)m0 * KDIM;
    const __half* b0p = B + ((size_t)z * NPIX + n0) * KDIM;

    float acc[4][4][4];
    #pragma unroll
    for (int i = 0; i < 4; i++)
        #pragma unroll
        for (int j = 0; j < 4; j++)
            #pragma unroll
            for (int k = 0; k < 4; k++) acc[i][j][k] = 0.f;

    gemm_load_stage(sm, 0, 0, tid, a0p, b0p);
    gemm_load_stage(sm, 1, 1, tid, a0p, b0p);

    int a_row = wm * 64 + ((lane >> 3) & 1) * 8 + (lane & 7);
    int a_ck  = (lane >> 4);
    int b_row = wn * 32 + (lane >> 4) * 8 + (lane & 7);
    int b_ck  = ((lane >> 3) & 1);
    uint32_t sbase = smem_u32(sm);

    for (int ck = 0; ck < 8; ck++) {
        if (ck + 2 < 8) {
            gemm_load_stage(sm, (ck + 2) % 3, ck + 2, tid, a0p, b0p);
            CP_WAIT(2);
        } else if (ck + 1 < 8) {
            CP_WAIT(1);
        } else {
            CP_WAIT(0);
        }
        __syncthreads();

        uint32_t st = sbase + (ck % 3) * STG;
        #pragma unroll
        for (int kk = 0; kk < 4; kk++) {
            uint32_t af[4][4];
            #pragma unroll
            for (int mf = 0; mf < 4; mf++) {
                int row = a_row + mf * 16;
                int chv = (kk * 2 + a_ck) ^ (row & 7);
                LDSM4(af[mf], st + row * 128 + (chv << 4));
            }
            uint32_t bf[2][4];
            #pragma unroll
            for (int ng = 0; ng < 2; ng++) {
                int row = b_row + ng * 16;
                int chv = (kk * 2 + b_ck) ^ (row & 7);
                LDSM4(bf[ng], st + 16384 + row * 128 + (chv << 4));
            }
            #pragma unroll
            for (int mf = 0; mf < 4; mf++)
                #pragma unroll
                for (int ng = 0; ng < 2; ng++)
                    #pragma unroll
                    for (int nh = 0; nh < 2; nh++)
                        MMA16816(acc[mf][ng * 2 + nh], af[mf],
                                 bf[ng][nh * 2], bf[ng][nh * 2 + 1]);
        }
        __syncthreads();
    }

    size_t obase = (size_t)z * M * NPIX;
    if (Ch) {
        #pragma unroll
        for (int mf = 0; mf < 4; mf++) {
            int m = m0 + wm * 64 + mf * 16 + (lane >> 2);
            #pragma unroll
            for (int nf = 0; nf < 4; nf++) {
                int n = n0 + wn * 32 + nf * 8 + (lane & 3) * 2;
                *(  __half2*)&Ch[obase + (size_t)m * NPIX + n] =
                    __floats2half2_rn(acc[mf][nf][0], acc[mf][nf][1]);
                *(__half2*)&Ch[obase + (size_t)(m + 8) * NPIX + n] =
                    __floats2half2_rn(acc[mf][nf][2], acc[mf][nf][3]);
            }
        }
    } else {
        #pragma unroll
        for (int mf = 0; mf < 4; mf++) {
            int m = m0 + wm * 64 + mf * 16 + (lane >> 2);
            float bb0 = bias ? bias[m] : 0.f;
            float bb8 = bias ? bias[m + 8] : 0.f;
            #pragma unroll
            for (int nf = 0; nf < 4; nf++) {
                int n = n0 + wn * 32 + nf * 8 + (lane & 3) * 2;
                *(float2*)&Cf[obase + (size_t)m * NPIX + n] =
                    make_float2(acc[mf][nf][0] + bb0, acc[mf][nf][1] + bb0);
                *(float2*)&Cf[obase + (size_t)(m + 8) * NPIX + n] =
                    make_float2(acc[mf][nf][2] + bb8, acc[mf][nf][3] + bb8);
            }
        }
    }
}

// ---------------------------------------------------------------------------
// qlhat: normalized latent queries (batch-invariant). grid=8, 256 threads.
// ---------------------------------------------------------------------------
__global__ __launch_bounds__(256) void qlhat_kernel(
    const float* __restrict__ w_q_lat, const float* __restrict__ latents,
    float* __restrict__ qlhat)
{
    int h = blockIdx.x;
    __shared__ float slat[C][L];
    __shared__ float stile[DH][L];
    __shared__ float snorm[L];
    int tid = threadIdx.x;
    for (int i = tid; i < C * L; i += 256) slat[i >> 4][i & 15] = latents[i];
    __syncthreads();
    for (int p = tid; p < DH * L; p += 256) {
        int j = p >> 4, l = p & 15;
        const float* wrow = w_q_lat + (size_t)(h * DH + j) * C;
        float acc = 0.f;
        for (int c2 = 0; c2 < C; c2++) acc += wrow[c2] * slat[c2][l];
        stile[j][l] = acc;
    }
    __syncthreads();
    if (tid < L) {
        float s = 0.f;
        for (int j = 0; j < DH; j++) { float v = stile[j][tid]; s += v * v; }
        snorm[tid] = 1.f / fmaxf(sqrtf(s), EPSN);
    }
    __syncthreads();
    for (int p = tid; p < DH * L; p += 256)
        qlhat[(h * DH + (p >> 4)) * L + (p & 15)] = stile[p >> 4][p & 15] * snorm[p & 15];
}

// ---------------------------------------------------------------------------
// attn1a: exp(logits) + per-split L-sums. grid (64,4), 256 threads.
// thread t handles pixels {2t, 2t+1, 512+2t, 513+2t} via half2 loads.
// ---------------------------------------------------------------------------
__global__ __launch_bounds__(256) void attn1a_kernel(
    const __half* __restrict__ kvq, const float* __restrict__ qlhat,
    float* __restrict__ attn_g, float* __restrict__ lsum_g)
{
    int bh = blockIdx.x, split = blockIdx.y, b = bh >> 3, h = bh & 7;
    const __half* kbase = kvq + ((size_t)b * MROWS + h * DH) * NPIX + split * 1024;
    float* attn = attn_g + (size_t)bh * L * NPIX + split * 1024;

    __shared__ float sql[DH][L];
    __shared__ float wred[8][L];
    int tid = threadIdx.x;
    for (int i = tid; i < DH * L; i += 256)
        sql[i >> 4][i & 15] = qlhat[(h * DH + (i >> 4)) * L + (i & 15)];
    __syncthreads();

    float dot[4][L], nrm[4] = {0.f, 0.f, 0.f, 0.f}, lsum[L];
    #pragma unroll
    for (int l = 0; l < L; l++) lsum[l] = 0.f;
    #pragma unroll
    for (int i = 0; i < 4; i++)
        #pragma unroll
        for (int l = 0; l < L; l++) dot[i][l] = 0.f;

    for (int j = 0; j < DH; j++) {
        const __half* kj = kbase + (size_t)j * NPIX;
        __half2 a01 = *(const __half2*)(kj + 2 * tid);
        __half2 a23 = *(const __half2*)(kj + 512 + 2 * tid);
        float kv[4] = {__low2float(a01), __high2float(a01),
                       __low2float(a23), __high2float(a23)};
        #pragma unroll
        for (int i = 0; i < 4; i++) nrm[i] += kv[i] * kv[i];
        #pragma unroll
        for (int l = 0; l < L; l++) {
            float s = sql[j][l];
            #pragma unroll
            for (int i = 0; i < 4; i++) dot[i][l] += kv[i] * s;
        }
    }
    float inv[4];
    #pragma unroll
    for (int i = 0; i < 4; i++) inv[i] = SCALE / fmaxf(sqrtf(nrm[i]), EPSN);
    #pragma unroll
    for (int l = 0; l < L; l++) {
        float p0 = __expf(dot[0][l] * inv[0]);
        float p1 = __expf(dot[1][l] * inv[1]);
        float p2 = __expf(dot[2][l] * inv[2]);
        float p3 = __expf(dot[3][l] * inv[3]);
        lsum[l] += p0 + p1 + p2 + p3;
        *(float2*)&attn[(size_t)l * NPIX + 2 * tid] = make_float2(p0, p1);
        *(float2*)&attn[(size_t)l * NPIX + 512 + 2 * tid] = make_float2(p2, p3);
    }
    int lane = tid & 31, wrp = tid >> 5;
    #pragma unroll
    for (int l = 0; l < L; l++) {
        float v = lsum[l];
        #pragma unroll
        for (int o = 16; o; o >>= 1) v += __shfl_xor_sync(0xffffffffu, v, o);
        if (lane == 0) wred[wrp][l] = v;
    }
    __syncthreads();
    if (tid < L) {
        float s = 0.f;
        for (int w = 0; w < 8; w++) s += wred[w][tid];
        lsum_g[bh * 64 + split * 16 + tid] = s;
    }
}

// attn1b: sinv = 1/sum over splits. 1 block, 1024 threads.
__global__ __launch_bounds__(1024) void attn1b_kernel(
    const float* __restrict__ lsum_g, float* __restrict__ sinv_g)
{
    int tid = threadIdx.x;
    int bh = tid >> 4, l = tid & 15;
    float s = 0.f;
    #pragma unroll
    for (int sp = 0; sp < 4; sp++) s += lsum_g[bh * 64 + sp * 16 + l];
    sinv_g[bh * 16 + l] = 1.f / s;
}

// attn1c: partial P@V (fp16 V, half2 loads). grid (64,4), 512 threads.
__global__ __launch_bounds__(512) void attn1c_kernel(
    const __half* __restrict__ kvq, const float* __restrict__ attn_g,
    float* __restrict__ latpart)
{
    int bh = blockIdx.x, split = blockIdx.y, b = bh >> 3, h = bh & 7;
    const __half* vbase = kvq + ((size_t)b * MROWS + 512 + h * DH) * NPIX + split * 1024;
    const float* attn = attn_g + (size_t)bh * L * NPIX + split * 1024;
    int tid = threadIdx.x, lane = tid & 31, wrp = tid >> 5;

    float acc[4][L];
    #pragma unroll
    for (int jj = 0; jj < 4; jj++)
        #pragma unroll
        for (int l = 0; l < L; l++) acc[jj][l] = 0.f;

    for (int it = 0; it < 16; it++) {
        int n2 = it * 64 + lane * 2;
        float2 pv[L];
        #pragma unroll
        for (int l = 0; l < L; l++) pv[l] = *(const float2*)&attn[(size_t)l * NPIX + n2];
        #pragma unroll
        for (int jj = 0; jj < 4; jj++) {
            __half2 v2 = *(const __half2*)&vbase[(size_t)(wrp * 4 + jj) * NPIX + n2];
            float v0 = __low2float(v2), v1 = __high2float(v2);
            #pragma unroll
            for (int l = 0; l < L; l++) acc[jj][l] += v0 * pv[l].x + v1 * pv[l].y;
        }
    }
    #pragma unroll
    for (int jj = 0; jj < 4; jj++)
        #pragma unroll
        for (int l = 0; l < L; l++) {
            float v = acc[jj][l];
            #pragma unroll
            for (int o = 16; o; o >>= 1) v += __shfl_xor_sync(0xffffffffu, v, o);
            if (lane == 0)
                latpart[split * 65536 + bh * 1024 + (wrp * 4 + jj) * 16 + l] = v;
        }
}

// attn1d: reduce splits + scale by sinv -> latread. grid 256, 256 threads.
__global__ __launch_bounds__(256) void attn1d_kernel(
    const float* __restrict__ latpart, const float* __restrict__ sinv_g,
    float* __restrict__ latread)
{
    int e = blockIdx.x * 256 + threadIdx.x;
    int bh = e >> 10, rem = e & 1023, r = rem >> 4, l = rem & 15;
    float s = latpart[e] + latpart[65536 + e] + latpart[131072 + e] + latpart[196608 + e];
    int b = bh >> 3, h = bh & 7;
    latread[((size_t)b * C + h * DH + r) * L + l] = s * sinv_g[bh * 16 + l];
}

// ---------------------------------------------------------------------------
// kvl: kvl[b] = w_kv_lat @ lat_read[b]; normalize k-part per (head,l).
// ---------------------------------------------------------------------------
__global__ __launch_bounds__(256) void kvl_kernel(
    const float* __restrict__ w_kv_lat, const float* __restrict__ latread,
    float* __restrict__ kvl)
{
    int b = blockIdx.x, c0 = blockIdx.y * 64;
    __shared__ float slat[C][L];
    __shared__ float stile[64][L];
    __shared__ float snorm[L];
    int tid = threadIdx.x;
    const float* lr = latread + (size_t)b * C * L;
    for (int i = tid; i < C * L; i += 256) slat[i >> 4][i & 15] = lr[i];
    __syncthreads();
    for (int p = tid; p < 64 * L; p += 256) {
        int j = p >> 4, l = p & 15;
        const float* wrow = w_kv_lat + (size_t)(c0 + j) * C;
        float acc = 0.f;
        for (int c2 = 0; c2 < C; c2++) acc += wrow[c2] * slat[c2][l];
        stile[j][l] = acc;
    }
    __syncthreads();
    if (c0 < C) {
        if (tid < L) {
            float s = 0.f;
            for (int j = 0; j < 64; j++) { float v = stile[j][tid]; s += v * v; }
            snorm[tid] = 1.f / fmaxf(sqrtf(s), EPSN);
        }
        __syncthreads();
        for (int p = tid; p < 64 * L; p += 256)
            kvl[((size_t)b * 2 * C + c0 + (p >> 4)) * L + (p & 15)] =
                stile[p >> 4][p & 15] * snorm[p & 15];
    } else {
        for (int p = tid; p < 64 * L; p += 256)
            kvl[((size_t)b * 2 * C + c0 + (p >> 4)) * L + (p & 15)] = stile[p >> 4][p & 15];
    }
}

// ---------------------------------------------------------------------------
// attn2: latent write, fused per pixel; fp16 q in, fp16 xwT out.
// grid (32, HEADS, Bsz), 128 threads.
// ---------------------------------------------------------------------------
__global__ __launch_bounds__(128) void attn2_kernel(
    const __half* __restrict__ kvq, const float* __restrict__ kvl,
    __half* __restrict__ xwT)
{
    int b = blockIdx.z, h = blockIdx.y;
    int tid = threadIdx.x;
    int n = blockIdx.x * 128 + tid;
    __shared__ float skl[DH][L];
    __shared__ float svl[DH][L];
    __shared__ unsigned short sh[DH][128];

    const float* kvlb = kvl + (size_t)b * 2 * C * L;
    for (int i = tid; i < DH * L; i += 128) {
        skl[i >> 4][i & 15] = kvlb[(h * DH + (i >> 4)) * L + (i & 15)];
        svl[i >> 4][i & 15] = kvlb[(C + h * DH + (i >> 4)) * L + (i & 15)];
    }
    __syncthreads();

    const __half* qcol = kvq + ((size_t)b * MROWS + 1024 + h * DH) * NPIX + n;
    float dot[L], nrm = 0.f;
    #pragma unroll
    for (int l = 0; l < L; l++) dot[l] = 0.f;
    for (int j = 0; j < DH; j++) {
        float q = __half2float(qcol[(size_t)j * NPIX]);
        nrm += q * q;
        #pragma unroll
        for (int l = 0; l < L; l++) dot[l] += q * skl[j][l];
    }
    float inv = SCALE / fmaxf(sqrtf(nrm), EPSN);
    float s = 0.f;
    #pragma unroll
    for (int l = 0; l < L; l++) { dot[l] = __expf(dot[l] * inv); s += dot[l]; }
    float is = 1.f / s;

    for (int j = 0; j < DH; j++) {
        float a = 0.f;
        #pragma unroll
        for (int l = 0; l < L; l++) a += dot[l] * svl[j][l];
        sh[j][tid] = __half_as_ushort(__float2half_rn(a * is));
    }
    __syncthreads();

    size_t base = ((size_t)b * NPIX + n) * C + h * DH;
    #pragma unroll
    for (int c4 = 0; c4 < 8; c4++) {
        uint32_t wv[4];
        #pragma unroll
        for (int k = 0; k < 4; k++) {
            int j = c4 * 8 + k * 2;
            wv[k] = (uint32_t)sh[j][tid] | ((uint32_t)sh[j + 1][tid] << 16);
        }
        *(uint4*)(xwT + base + c4 * 8) = make_uint4(wv[0], wv[1], wv[2], wv[3]);
    }
}

// ---------------------------------------------------------------------------
// Launch
// ---------------------------------------------------------------------------
extern "C" void kernel_launch(void* const* d_in, const int* in_sizes, int n_in,
                              void* d_out, int out_size)
{
    const float* x        = (const float*)d_in[0];
    const float* latents  = (const float*)d_in[1];
    const float* w_q_lat  = (const float*)d_in[2];
    const float* w_kv_x   = (const float*)d_in[3];
    const float* w_q_x    = (const float*)d_in[4];
    const float* w_kv_lat = (const float*)d_in[5];
    const float* w_proj   = (const float*)d_in[6];
    const float* b_proj   = (const float*)d_in[7];
    float* out = (float*)d_out;

    float *attn, *lsum, *sinv, *latpart, *latread, *kvl, *qlhat;
    __half *kvq, *xT, *xwT, *wA, *wp;
    cudaGetSymbolAddress((void**)&kvq, g_kvq);
    cudaGetSymbolAddress((void**)&attn, g_attn);
    cudaGetSymbolAddress((void**)&lsum, g_lsum);
    cudaGetSymbolAddress((void**)&sinv, g_sinv);
    cudaGetSymbolAddress((void**)&latpart, g_latpart);
    cudaGetSymbolAddress((void**)&latread, g_latread);
    cudaGetSymbolAddress((void**)&kvl, g_kvl);
    cudaGetSymbolAddress((void**)&qlhat, g_qlhat);
    cudaGetSymbolAddress((void**)&xT, g_xT);
    cudaGetSymbolAddress((void**)&xwT, g_xwT);
    cudaGetSymbolAddress((void**)&wA, g_wA);
    cudaGetSymbolAddress((void**)&wp, g_wp);

    cudaFuncSetAttribute(gemm_mma, cudaFuncAttributeMaxDynamicSharedMemorySize, 3 * STG);

    // operand preparation
    wconv_kernel<<<(2 * C * KDIM / 4 + 255) / 256, 256>>>(w_kv_x, wA, 2 * C * KDIM / 4);
    wconv_kernel<<<(C * KDIM / 4 + 255) / 256, 256>>>(w_q_x, wA + 2 * C * KDIM, C * KDIM / 4);
    wconv_kernel<<<(C * KDIM / 4 + 255) / 256, 256>>>(w_proj, wp, C * KDIM / 4);
    tconv_kernel<<<dim3(NPIX / 32, C / 32, Bsz), dim3(32, 8)>>>(x, xT);
    qlhat_kernel<<<HEADS, 256>>>(w_q_lat, latents, qlhat);

    // fused kv+q GEMM (M=1536) -> fp16 kvq
    gemm_mma<<<dim3(32, 12, Bsz), 256, 3 * STG>>>(wA, xT, kvq, nullptr, nullptr, MROWS);

    // latent read attention
    attn1a_kernel<<<dim3(64, 4), 256>>>(kvq, qlhat, attn, lsum);
    attn1b_kernel<<<1, 1024>>>(lsum, sinv);
    attn1c_kernel<<<dim3(64, 4), 512>>>(kvq, attn, latpart);
    attn1d_kernel<<<256, 256>>>(latpart, sinv, latread);

    kvl_kernel<<<dim3(Bsz, 16), 256>>>(w_kv_lat, latread, kvl);

    // latent write attention -> fp16 xwT
    attn2_kernel<<<dim3(32, HEADS, Bsz), 128>>>(kvq, kvl, xwT);

    // output projection + bias (fp32 out)
    gemm_mma<<<dim3(32, 4, Bsz), 256, 3 * STG>>>(wp, xwT, nullptr, out, b_proj, 512);
}

// round 7
// speedup vs baseline: 4.2821x; 1.0359x over previous
#include <cuda_runtime.h>
#include <cuda_fp16.h>
#include <math.h>
#include <stdint.h>

// ---------------------------------------------------------------------------
// LatentMixer on GB300 (sm_103 plain target): single-term fp16 HMMA GEMMs
// + fused attention (attn1 one-pass, smem exp tile).
// B=8, C=512, N=4096, heads=8, d=64, L=16, scale=0.125
// ---------------------------------------------------------------------------

#define Bsz 8
#define C   512
#define NPIX 4096
#define L   16
#define HEADS 8
#define DH  64
#define SCALE 0.125f
#define EPSN 1e-12f
#define KDIM 512
#define MROWS 1536   // stacked k(512) v(512) q(512)

// ---------------- scratch (device globals; allocation-free contract) -------
__device__ __half g_kvq[(size_t)Bsz * MROWS * NPIX];   // fp16 k/v/q
__device__ float g_lsum[64 * 4 * L];
__device__ float g_sinv[64 * L];
__device__ float g_latpart[4 * 64 * DH * L];
__device__ float g_latread[Bsz * C * L];
__device__ float g_kvl[Bsz * 2 * C * L];
__device__ float g_qlhat[C * L];
__device__ __half g_xT [(size_t)Bsz * NPIX * C];       // x transposed fp16
__device__ __half g_xwT[(size_t)Bsz * NPIX * C];       // attn2 out fp16
__device__ __half g_wA[MROWS * KDIM];                  // stacked w_kv_x ; w_q_x
__device__ __half g_wp[C * KDIM];                      // w_proj

// ---------------- helpers ---------------------------------------------------
__device__ __forceinline__ uint32_t smem_u32(const void* p) {
    uint32_t a;
    asm("{ .reg .u64 t; cvta.to.shared.u64 t, %1; cvt.u32.u64 %0, t; }" : "=r"(a) : "l"(p));
    return a;
}

#define LDSM4(r, addr) \
    asm volatile("ldmatrix.sync.aligned.m8n8.x4.shared.b16 {%0,%1,%2,%3}, [%4];" \
                 : "=r"((r)[0]), "=r"((r)[1]), "=r"((r)[2]), "=r"((r)[3]) : "r"(addr))

#define MMA16816(cc, aa, b0, b1) \
    asm volatile("mma.sync.aligned.m16n8k16.row.col.f32.f16.f16.f32 " \
                 "{%0,%1,%2,%3}, {%4,%5,%6,%7}, {%8,%9}, {%0,%1,%2,%3};" \
                 : "+f"((cc)[0]), "+f"((cc)[1]), "+f"((cc)[2]), "+f"((cc)[3]) \
                 : "r"((aa)[0]), "r"((aa)[1]), "r"((aa)[2]), "r"((aa)[3]), \
                   "r"(b0), "r"(b1))

#define CP_ASYNC16(dst, src) \
    asm volatile("cp.async.cg.shared.global [%0], [%1], 16;" :: "r"(dst), "l"(src))
#define CP_COMMIT() asm volatile("cp.async.commit_group;" ::: "memory")
#define CP_WAIT(n)  asm volatile("cp.async.wait_group %0;" :: "n"(n) : "memory")

// ---------------------------------------------------------------------------
// Weight convert: fp32 -> fp16
// ---------------------------------------------------------------------------
__global__ __launch_bounds__(256) void wconv_kernel(
    const float* __restrict__ a, __half* __restrict__ hi, int n4)
{
    int i = blockIdx.x * 256 + threadIdx.x;
    if (i >= n4) return;
    float4 v = ((const float4*)a)[i];
    __half2* o = (__half2*)(hi + i * 4);
    o[0] = __floats2half2_rn(v.x, v.y);
    o[1] = __floats2half2_rn(v.z, v.w);
}

// ---------------------------------------------------------------------------
// Transpose x: [B,C,N] fp32 -> [B,N,C] fp16. 32x32 tiles.
// ---------------------------------------------------------------------------
__global__ __launch_bounds__(256) void tconv_kernel(
    const float* __restrict__ x, __half* __restrict__ xo)
{
    __shared__ float t[32][33];
    int n0 = blockIdx.x * 32, c0 = blockIdx.y * 32, b = blockIdx.z;
    int tx = threadIdx.x, ty = threadIdx.y;
    const float* xb = x + (size_t)b * C * NPIX;
    #pragma unroll
    for (int i = 0; i < 4; i++)
        t[ty + i * 8][tx] = xb[(size_t)(c0 + ty + i * 8) * NPIX + n0 + tx];
    __syncthreads();
    __half* ob = xo + (size_t)b * NPIX * C;
    #pragma unroll
    for (int i = 0; i < 4; i++)
        ob[(size_t)(n0 + ty + i * 8) * C + c0 + tx] = __float2half_rn(t[tx][ty + i * 8]);
}

// ---------------------------------------------------------------------------
// HMMA GEMM: C[z][m][n] = sum_k A[m][k]*B[z][n][k], single fp16 term.
// Tile 128x128x64, 256 threads (2x4 warps, warp tile 64x32), 3-stage cp.async.
// 2 CTAs/SM. Output: fp16 (Ch) or fp32+bias (Cf).
// ---------------------------------------------------------------------------
#define STG 32768
__device__ __forceinline__ void gemm_load_stage(
    char* sm, int stg, int ck, int tid,
    const __half* a0, const __half* b0)
{
    char* d = sm + stg * STG;
    #pragma unroll
    for (int i = 0; i < 8; i++) {
        int u = tid + i * 256;
        int r = u >> 10, idx = u & 1023, row = idx >> 3, c = idx & 7;
        const __half* src = ((r == 0) ? a0 : b0) + (size_t)row * KDIM + ck * 64 + c * 8;
        uint32_t dst = smem_u32(d + r * 16384 + row * 128 + (((c ^ (row & 7))) << 4));
        CP_ASYNC16(dst, src);
    }
    CP_COMMIT();
}

__global__ __launch_bounds__(256, 2) void gemm_mma(
    const __half* __restrict__ A, const __half* __restrict__ B,
    __half* __restrict__ Ch, float* __restrict__ Cf,
    const float* __restrict__ bias, int M)
{
    extern __shared__ char sm[];
    int tid = threadIdx.x, lane = tid & 31, wid = tid >> 5;
    int wm = wid >> 2, wn = wid & 3;
    int m0 = blockIdx.y * 128, n0 = blockIdx.x * 128, z = blockIdx.z;

    const __half* a0p = A + (size_t)m0 * KDIM;
    const __half* b0p = B + ((size_t)z * NPIX + n0) * KDIM;

    float acc[4][4][4];
    #pragma unroll
    for (int i = 0; i < 4; i++)
        #pragma unroll
        for (int j = 0; j < 4; j++)
            #pragma unroll
            for (int k = 0; k < 4; k++) acc[i][j][k] = 0.f;

    gemm_load_stage(sm, 0, 0, tid, a0p, b0p);
    gemm_load_stage(sm, 1, 1, tid, a0p, b0p);

    int a_row = wm * 64 + ((lane >> 3) & 1) * 8 + (lane & 7);
    int a_ck  = (lane >> 4);
    int b_row = wn * 32 + (lane >> 4) * 8 + (lane & 7);
    int b_ck  = ((lane >> 3) & 1);
    uint32_t sbase = smem_u32(sm);

    for (int ck = 0; ck < 8; ck++) {
        if (ck + 2 < 8) {
            gemm_load_stage(sm, (ck + 2) % 3, ck + 2, tid, a0p, b0p);
            CP_WAIT(2);
        } else if (ck + 1 < 8) {
            CP_WAIT(1);
        } else {
            CP_WAIT(0);
        }
        __syncthreads();

        uint32_t st = sbase + (ck % 3) * STG;
        #pragma unroll
        for (int kk = 0; kk < 4; kk++) {
            uint32_t af[4][4];
            #pragma unroll
            for (int mf = 0; mf < 4; mf++) {
                int row = a_row + mf * 16;
                int chv = (kk * 2 + a_ck) ^ (row & 7);
                LDSM4(af[mf], st + row * 128 + (chv << 4));
            }
            uint32_t bf[2][4];
            #pragma unroll
            for (int ng = 0; ng < 2; ng++) {
                int row = b_row + ng * 16;
                int chv = (kk * 2 + b_ck) ^ (row & 7);
                LDSM4(bf[ng], st + 16384 + row * 128 + (chv << 4));
            }
            #pragma unroll
            for (int mf = 0; mf < 4; mf++)
                #pragma unroll
                for (int ng = 0; ng < 2; ng++)
                    #pragma unroll
                    for (int nh = 0; nh < 2; nh++)
                        MMA16816(acc[mf][ng * 2 + nh], af[mf],
                                 bf[ng][nh * 2], bf[ng][nh * 2 + 1]);
        }
        __syncthreads();
    }

    size_t obase = (size_t)z * M * NPIX;
    if (Ch) {
        #pragma unroll
        for (int mf = 0; mf < 4; mf++) {
            int m = m0 + wm * 64 + mf * 16 + (lane >> 2);
            #pragma unroll
            for (int nf = 0; nf < 4; nf++) {
                int n = n0 + wn * 32 + nf * 8 + (lane & 3) * 2;
                *(__half2*)&Ch[obase + (size_t)m * NPIX + n] =
                    __floats2half2_rn(acc[mf][nf][0], acc[mf][nf][1]);
                *(__half2*)&Ch[obase + (size_t)(m + 8) * NPIX + n] =
                    __floats2half2_rn(acc[mf][nf][2], acc[mf][nf][3]);
            }
        }
    } else {
        #pragma unroll
        for (int mf = 0; mf < 4; mf++) {
            int m = m0 + wm * 64 + mf * 16 + (lane >> 2);
            float bb0 = bias ? bias[m] : 0.f;
            float bb8 = bias ? bias[m + 8] : 0.f;
            #pragma unroll
            for (int nf = 0; nf < 4; nf++) {
                int n = n0 + wn * 32 + nf * 8 + (lane & 3) * 2;
                *(float2*)&Cf[obase + (size_t)m * NPIX + n] =
                    make_float2(acc[mf][nf][0] + bb0, acc[mf][nf][1] + bb0);
                *(float2*)&Cf[obase + (size_t)(m + 8) * NPIX + n] =
                    make_float2(acc[mf][nf][2] + bb8, acc[mf][nf][3] + bb8);
            }
        }
    }
}

// ---------------------------------------------------------------------------
// qlhat: normalized latent queries (batch-invariant). grid=8, 256 threads.
// ---------------------------------------------------------------------------
__global__ __launch_bounds__(256) void qlhat_kernel(
    const float* __restrict__ w_q_lat, const float* __restrict__ latents,
    float* __restrict__ qlhat)
{
    int h = blockIdx.x;
    __shared__ float slat[C][L];
    __shared__ float stile[DH][L];
    __shared__ float snorm[L];
    int tid = threadIdx.x;
    for (int i = tid; i < C * L; i += 256) slat[i >> 4][i & 15] = latents[i];
    __syncthreads();
    for (int p = tid; p < DH * L; p += 256) {
        int j = p >> 4, l = p & 15;
        const float* wrow = w_q_lat + (size_t)(h * DH + j) * C;
        float acc = 0.f;
        for (int c2 = 0; c2 < C; c2++) acc += wrow[c2] * slat[c2][l];
        stile[j][l] = acc;
    }
    __syncthreads();
    if (tid < L) {
        float s = 0.f;
        for (int j = 0; j < DH; j++) { float v = stile[j][tid]; s += v * v; }
        snorm[tid] = 1.f / fmaxf(sqrtf(s), EPSN);
    }
    __syncthreads();
    for (int p = tid; p < DH * L; p += 256)
        qlhat[(h * DH + (p >> 4)) * L + (p & 15)] = stile[p >> 4][p & 15] * snorm[p & 15];
}

// ---------------------------------------------------------------------------
// attn1 fused: per (bh, split of 1024 px): exp(logits) -> smem tile [16][1024],
// per-split L-sums -> lsum_g, unnormalized partial P@V -> latpart.
// grid (64, 4), 512 threads, ~69KB dynamic smem.
// ---------------------------------------------------------------------------
__global__ __launch_bounds__(512) void attn1_fused_kernel(
    const __half* __restrict__ kvq, const float* __restrict__ qlhat,
    float* __restrict__ latpart, float* __restrict__ lsum_g)
{
    extern __shared__ float dyn[];
    float* p_sm = dyn;                       // [16][1024] = 64KB
    float (*sql)[L] = (float(*)[L])(dyn + L * 1024);   // [64][16]
    float (*wred)[L] = (float(*)[L])(dyn + L * 1024 + DH * L); // [16][16]

    int bh = blockIdx.x, split = blockIdx.y, b = bh >> 3, h = bh & 7;
    const __half* kbase = kvq + ((size_t)b * MROWS + h * DH) * NPIX + split * 1024;
    const __half* vbase = kvq + ((size_t)b * MROWS + 512 + h * DH) * NPIX + split * 1024;
    int tid = threadIdx.x, lane = tid & 31, wrp = tid >> 5;

    for (int i = tid; i < DH * L; i += 512)
        sql[i >> 4][i & 15] = qlhat[(h * DH + (i >> 4)) * L + (i & 15)];
    __syncthreads();

    // phase 1: 2 pixels per thread (2*tid, 2*tid+1)
    {
        float dot[2][L], nrm[2] = {0.f, 0.f};
        #pragma unroll
        for (int i = 0; i < 2; i++)
            #pragma unroll
            for (int l = 0; l < L; l++) dot[i][l] = 0.f;
        for (int j = 0; j < DH; j++) {
            __half2 a01 = *(const __half2*)(kbase + (size_t)j * NPIX + 2 * tid);
            float k0 = __low2float(a01), k1 = __high2float(a01);
            nrm[0] += k0 * k0; nrm[1] += k1 * k1;
            #pragma unroll
            for (int l = 0; l < L; l++) {
                float s = sql[j][l];
                dot[0][l] += k0 * s;
                dot[1][l] += k1 * s;
            }
        }
        float inv0 = SCALE / fmaxf(sqrtf(nrm[0]), EPSN);
        float inv1 = SCALE / fmaxf(sqrtf(nrm[1]), EPSN);
        float lsum[L];
        #pragma unroll
        for (int l = 0; l < L; l++) {
            float p0 = __expf(dot[0][l] * inv0);
            float p1 = __expf(dot[1][l] * inv1);
            lsum[l] = p0 + p1;
            *(float2*)&p_sm[l * 1024 + 2 * tid] = make_float2(p0, p1);
        }
        #pragma unroll
        for (int l = 0; l < L; l++) {
            float v = lsum[l];
            #pragma unroll
            for (int o = 16; o; o >>= 1) v += __shfl_xor_sync(0xffffffffu, v, o);
            if (lane == 0) wred[wrp][l] = v;
        }
    }
    __syncthreads();
    if (tid < L) {
        float s = 0.f;
        #pragma unroll
        for (int w = 0; w < 16; w++) s += wred[w][tid];
        lsum_g[bh * 64 + split * 16 + tid] = s;
    }

    // phase 2: warp wrp owns rows j in [4*wrp, 4*wrp+4); unnormalized P@V
    float acc[4][L];
    #pragma unroll
    for (int jj = 0; jj < 4; jj++)
        #pragma unroll
        for (int l = 0; l < L; l++) acc[jj][l] = 0.f;

    for (int it = 0; it < 16; it++) {
        int n2 = it * 64 + lane * 2;
        float2 pv[L];
        #pragma unroll
        for (int l = 0; l < L; l++) pv[l] = *(const float2*)&p_sm[l * 1024 + n2];
        #pragma unroll
        for (int jj = 0; jj < 4; jj++) {
            __half2 v2 = *(const __half2*)&vbase[(size_t)(wrp * 4 + jj) * NPIX + n2];
            float v0 = __low2float(v2), v1 = __high2float(v2);
            #pragma unroll
            for (int l = 0; l < L; l++) acc[jj][l] += v0 * pv[l].x + v1 * pv[l].y;
        }
    }
    #pragma unroll
    for (int jj = 0; jj < 4; jj++)
        #pragma unroll
        for (int l = 0; l < L; l++) {
            float v = acc[jj][l];
            #pragma unroll
            for (int o = 16; o; o >>= 1) v += __shfl_xor_sync(0xffffffffu, v, o);
            if (lane == 0)
                latpart[split * 65536 + bh * 1024 + (wrp * 4 + jj) * 16 + l] = v;
        }
}

// attn1b: sinv = 1/sum over splits. 1 block, 1024 threads.
__global__ __launch_bounds__(1024) void attn1b_kernel(
    const float* __restrict__ lsum_g, float* __restrict__ sinv_g)
{
    int tid = threadIdx.x;
    int bh = tid >> 4, l = tid & 15;
    float s = 0.f;
    #pragma unroll
    for (int sp = 0; sp < 4; sp++) s += lsum_g[bh * 64 + sp * 16 + l];
    sinv_g[bh * 16 + l] = 1.f / s;
}

// attn1d: reduce splits + scale by sinv -> latread. grid 256, 256 threads.
__global__ __launch_bounds__(256) void attn1d_kernel(
    const float* __restrict__ latpart, const float* __restrict__ sinv_g,
    float* __restrict__ latread)
{
    int e = blockIdx.x * 256 + threadIdx.x;
    int bh = e >> 10, rem = e & 1023, r = rem >> 4, l = rem & 15;
    float s = latpart[e] + latpart[65536 + e] + latpart[131072 + e] + latpart[196608 + e];
    int b = bh >> 3, h = bh & 7;
    latread[((size_t)b * C + h * DH + r) * L + l] = s * sinv_g[bh * 16 + l];
}

// ---------------------------------------------------------------------------
// kvl: kvl[b] = w_kv_lat @ lat_read[b]; normalize k-part per (head,l).
// ---------------------------------------------------------------------------
__global__ __launch_bounds__(256) void kvl_kernel(
    const float* __restrict__ w_kv_lat, const float* __restrict__ latread,
    float* __restrict__ kvl)
{
    int b = blockIdx.x, c0 = blockIdx.y * 64;
    __shared__ float slat[C][L];
    __shared__ float stile[64][L];
    __shared__ float snorm[L];
    int tid = threadIdx.x;
    const float* lr = latread + (size_t)b * C * L;
    for (int i = tid; i < C * L; i += 256) slat[i >> 4][i & 15] = lr[i];
    __syncthreads();
    for (int p = tid; p < 64 * L; p += 256) {
        int j = p >> 4, l = p & 15;
        const float* wrow = w_kv_lat + (size_t)(c0 + j) * C;
        float acc = 0.f;
        for (int c2 = 0; c2 < C; c2++) acc += wrow[c2] * slat[c2][l];
        stile[j][l] = acc;
    }
    __syncthreads();
    if (c0 < C) {
        if (tid < L) {
            float s = 0.f;
            for (int j = 0; j < 64; j++) { float v = stile[j][tid]; s += v * v; }
            snorm[tid] = 1.f / fmaxf(sqrtf(s), EPSN);
        }
        __syncthreads();
        for (int p = tid; p < 64 * L; p += 256)
            kvl[((size_t)b * 2 * C + c0 + (p >> 4)) * L + (p & 15)] =
                stile[p >> 4][p & 15] * snorm[p & 15];
    } else {
        for (int p = tid; p < 64 * L; p += 256)
            kvl[((size_t)b * 2 * C + c0 + (p >> 4)) * L + (p & 15)] = stile[p >> 4][p & 15];
    }
}

// ---------------------------------------------------------------------------
// attn2: latent write, fused per pixel; fp16 q in, fp16 xwT out.
// grid (32, HEADS, Bsz), 128 threads.
// ---------------------------------------------------------------------------
__global__ __launch_bounds__(128) void attn2_kernel(
    const __half* __restrict__ kvq, const float* __restrict__ kvl,
    __half* __restrict__ xwT)
{
    int b = blockIdx.z, h = blockIdx.y;
    int tid = threadIdx.x;
    int n = blockIdx.x * 128 + tid;
    __shared__ float skl[DH][L];
    __shared__ float svl[DH][L];
    __shared__ unsigned short sh[DH][128];

    const float* kvlb = kvl + (size_t)b * 2 * C * L;
    for (int i = tid; i < DH * L; i += 128) {
        skl[i >> 4][i & 15] = kvlb[(h * DH + (i >> 4)) * L + (i & 15)];
        svl[i >> 4][i & 15] = kvlb[(C + h * DH + (i >> 4)) * L + (i & 15)];
    }
    __syncthreads();

    const __half* qcol = kvq + ((size_t)b * MROWS + 1024 + h * DH) * NPIX + n;
    float dot[L], nrm = 0.f;
    #pragma unroll
    for (int l = 0; l < L; l++) dot[l] = 0.f;
    for (int j = 0; j < DH; j++) {
        float q = __half2float(qcol[(size_t)j * NPIX]);
        nrm += q * q;
        #pragma unroll
        for (int l = 0; l < L; l++) dot[l] += q * skl[j][l];
    }
    float inv = SCALE / fmaxf(sqrtf(nrm), EPSN);
    float s = 0.f;
    #pragma unroll
    for (int l = 0; l < L; l++) { dot[l] = __expf(dot[l] * inv); s += dot[l]; }
    float is = 1.f / s;

    for (int j = 0; j < DH; j++) {
        float a = 0.f;
        #pragma unroll
        for (int l = 0; l < L; l++) a += dot[l] * svl[j][l];
        sh[j][tid] = __half_as_ushort(__float2half_rn(a * is));
    }
    __syncthreads();

    size_t base = ((size_t)b * NPIX + n) * C + h * DH;
    #pragma unroll
    for (int c4 = 0; c4 < 8; c4++) {
        uint32_t wv[4];
        #pragma unroll
        for (int k = 0; k < 4; k++) {
            int j = c4 * 8 + k * 2;
            wv[k] = (uint32_t)sh[j][tid] | ((uint32_t)sh[j + 1][tid] << 16);
        }
        *(uint4*)(xwT + base + c4 * 8) = make_uint4(wv[0], wv[1], wv[2], wv[3]);
    }
}

// ---------------------------------------------------------------------------
// Launch
// ---------------------------------------------------------------------------
extern "C" void kernel_launch(void* const* d_in, const int* in_sizes, int n_in,
                              void* d_out, int out_size)
{
    const float* x        = (const float*)d_in[0];
    const float* latents  = (const float*)d_in[1];
    const float* w_q_lat  = (const float*)d_in[2];
    const float* w_kv_x   = (const float*)d_in[3];
    const float* w_q_x    = (const float*)d_in[4];
    const float* w_kv_lat = (const float*)d_in[5];
    const float* w_proj   = (const float*)d_in[6];
    const float* b_proj   = (const float*)d_in[7];
    float* out = (float*)d_out;

    float *lsum, *sinv, *latpart, *latread, *kvl, *qlhat;
    __half *kvq, *xT, *xwT, *wA, *wp;
    cudaGetSymbolAddress((void**)&kvq, g_kvq);
    cudaGetSymbolAddress((void**)&lsum, g_lsum);
    cudaGetSymbolAddress((void**)&sinv, g_sinv);
    cudaGetSymbolAddress((void**)&latpart, g_latpart);
    cudaGetSymbolAddress((void**)&latread, g_latread);
    cudaGetSymbolAddress((void**)&kvl, g_kvl);
    cudaGetSymbolAddress((void**)&qlhat, g_qlhat);
    cudaGetSymbolAddress((void**)&xT, g_xT);
    cudaGetSymbolAddress((void**)&xwT, g_xwT);
    cudaGetSymbolAddress((void**)&wA, g_wA);
    cudaGetSymbolAddress((void**)&wp, g_wp);

    cudaFuncSetAttribute(gemm_mma, cudaFuncAttributeMaxDynamicSharedMemorySize, 3 * STG);
    int attn1_smem = (L * 1024 + DH * L + 16 * L) * sizeof(float);
    cudaFuncSetAttribute(attn1_fused_kernel, cudaFuncAttributeMaxDynamicSharedMemorySize, attn1_smem);

    // operand preparation
    wconv_kernel<<<(2 * C * KDIM / 4 + 255) / 256, 256>>>(w_kv_x, wA, 2 * C * KDIM / 4);
    wconv_kernel<<<(C * KDIM / 4 + 255) / 256, 256>>>(w_q_x, wA + 2 * C * KDIM, C * KDIM / 4);
    wconv_kernel<<<(C * KDIM / 4 + 255) / 256, 256>>>(w_proj, wp, C * KDIM / 4);
    tconv_kernel<<<dim3(NPIX / 32, C / 32, Bsz), dim3(32, 8)>>>(x, xT);
    qlhat_kernel<<<HEADS, 256>>>(w_q_lat, latents, qlhat);

    // fused kv+q GEMM (M=1536) -> fp16 kvq
    gemm_mma<<<dim3(32, 12, Bsz), 256, 3 * STG>>>(wA, xT, kvq, nullptr, nullptr, MROWS);

    // latent read attention (fused exp + partial P@V)
    attn1_fused_kernel<<<dim3(64, 4), 512, attn1_smem>>>(kvq, qlhat, latpart, lsum);
    attn1b_kernel<<<1, 1024>>>(lsum, sinv);
    attn1d_kernel<<<256, 256>>>(latpart, sinv, latread);

    kvl_kernel<<<dim3(Bsz, 16), 256>>>(w_kv_lat, latread, kvl);

    // latent write attention -> fp16 xwT
    attn2_kernel<<<dim3(32, HEADS, Bsz), 128>>>(kvq, kvl, xwT);

    // output projection + bias (fp32 out)
    gemm_mma<<<dim3(32, 4, Bsz), 256, 3 * STG>>>(wp, xwT, nullptr, out, b_proj, 512);
}

// round 8
// speedup vs baseline: 4.8419x; 1.1307x over previous
#include <cuda_runtime.h>
#include <cuda_fp16.h>
#include <math.h>
#include <stdint.h>

// ---------------------------------------------------------------------------
// LatentMixer on GB300 (sm_103 plain target): single-term fp16 HMMA GEMMs
// + fused attention; side-stream overlap for operand prep.
// B=8, C=512, N=4096, heads=8, d=64, L=16, scale=0.125
// ---------------------------------------------------------------------------

#define Bsz 8
#define C   512
#define NPIX 4096
#define L   16
#define HEADS 8
#define DH  64
#define SCALE 0.125f
#define EPSN 1e-12f
#define KDIM 512
#define MROWS 1536   // stacked k(512) v(512) q(512)

// ---------------- scratch (device globals; allocation-free contract) -------
__device__ __half g_kvq[(size_t)Bsz * MROWS * NPIX];   // fp16 k/v/q
__device__ float g_lsum[64 * 4 * L];
__device__ float g_latpart[4 * 64 * DH * L];
__device__ float g_latread[Bsz * C * L];
__device__ float g_kvl[Bsz * 2 * C * L];
__device__ float g_qlhat[C * L];
__device__ __half g_xT [(size_t)Bsz * NPIX * C];       // x transposed fp16
__device__ __half g_xwT[(size_t)Bsz * NPIX * C];       // attn2 out fp16
__device__ __half g_wA[MROWS * KDIM];                  // stacked w_kv_x ; w_q_x
__device__ __half g_wp[C * KDIM];                      // w_proj

// ---------------- helpers ---------------------------------------------------
__device__ __forceinline__ uint32_t smem_u32(const void* p) {
    uint32_t a;
    asm("{ .reg .u64 t; cvta.to.shared.u64 t, %1; cvt.u32.u64 %0, t; }" : "=r"(a) : "l"(p));
    return a;
}

#define LDSM4(r, addr) \
    asm volatile("ldmatrix.sync.aligned.m8n8.x4.shared.b16 {%0,%1,%2,%3}, [%4];" \
                 : "=r"((r)[0]), "=r"((r)[1]), "=r"((r)[2]), "=r"((r)[3]) : "r"(addr))

#define MMA16816(cc, aa, b0, b1) \
    asm volatile("mma.sync.aligned.m16n8k16.row.col.f32.f16.f16.f32 " \
                 "{%0,%1,%2,%3}, {%4,%5,%6,%7}, {%8,%9}, {%0,%1,%2,%3};" \
                 : "+f"((cc)[0]), "+f"((cc)[1]), "+f"((cc)[2]), "+f"((cc)[3]) \
                 : "r"((aa)[0]), "r"((aa)[1]), "r"((aa)[2]), "r"((aa)[3]), \
                   "r"(b0), "r"(b1))

#define CP_ASYNC16(dst, src) \
    asm volatile("cp.async.cg.shared.global [%0], [%1], 16;" :: "r"(dst), "l"(src))
#define CP_COMMIT() asm volatile("cp.async.commit_group;" ::: "memory")
#define CP_WAIT(n)  asm volatile("cp.async.wait_group %0;" :: "n"(n) : "memory")

// ---------------------------------------------------------------------------
// Weight convert: fp32 -> fp16
// ---------------------------------------------------------------------------
__global__ __launch_bounds__(256) void wconv_kernel(
    const float* __restrict__ a, __half* __restrict__ hi, int n4)
{
    int i = blockIdx.x * 256 + threadIdx.x;
    if (i >= n4) return;
    float4 v = ((const float4*)a)[i];
    __half2* o = (__half2*)(hi + i * 4);
    o[0] = __floats2half2_rn(v.x, v.y);
    o[1] = __floats2half2_rn(v.z, v.w);
}

// ---------------------------------------------------------------------------
// Transpose x: [B,C,N] fp32 -> [B,N,C] fp16. 32x32 tiles.
// ---------------------------------------------------------------------------
__global__ __launch_bounds__(256) void tconv_kernel(
    const float* __restrict__ x, __half* __restrict__ xo)
{
    __shared__ float t[32][33];
    int n0 = blockIdx.x * 32, c0 = blockIdx.y * 32, b = blockIdx.z;
    int tx = threadIdx.x, ty = threadIdx.y;
    const float* xb = x + (size_t)b * C * NPIX;
    #pragma unroll
    for (int i = 0; i < 4; i++)
        t[ty + i * 8][tx] = xb[(size_t)(c0 + ty + i * 8) * NPIX + n0 + tx];
    __syncthreads();
    __half* ob = xo + (size_t)b * NPIX * C;
    #pragma unroll
    for (int i = 0; i < 4; i++)
        ob[(size_t)(n0 + ty + i * 8) * C + c0 + tx] = __float2half_rn(t[tx][ty + i * 8]);
}

// ---------------------------------------------------------------------------
// HMMA GEMM: C[z][m][n] = sum_k A[m][k]*B[z][n][k], single fp16 term.
// Tile 128x128x64, 256 threads (2x4 warps, warp tile 64x32), 3-stage cp.async.
// 2 CTAs/SM. Output: fp16 (Ch) or fp32+bias (Cf).
// ---------------------------------------------------------------------------
#define STG 32768
__device__ __forceinline__ void gemm_load_stage(
    char* sm, int stg, int ck, int tid,
    const __half* a0, const __half* b0)
{
    char* d = sm + stg * STG;
    #pragma unroll
    for (int i = 0; i < 8; i++) {
        int u = tid + i * 256;
        int r = u >> 10, idx = u & 1023, row = idx >> 3, c = idx & 7;
        const __half* src = ((r == 0) ? a0 : b0) + (size_t)row * KDIM + ck * 64 + c * 8;
        uint32_t dst = smem_u32(d + r * 16384 + row * 128 + (((c ^ (row & 7))) << 4));
        CP_ASYNC16(dst, src);
    }
    CP_COMMIT();
}

__global__ __launch_bounds__(256, 2) void gemm_mma(
    const __half* __restrict__ A, const __half* __restrict__ B,
    __half* __restrict__ Ch, float* __restrict__ Cf,
    const float* __restrict__ bias, int M)
{
    extern __shared__ char sm[];
    int tid = threadIdx.x, lane = tid & 31, wid = tid >> 5;
    int wm = wid >> 2, wn = wid & 3;
    int m0 = blockIdx.y * 128, n0 = blockIdx.x * 128, z = blockIdx.z;

    const __half* a0p = A + (size_t)m0 * KDIM;
    const __half* b0p = B + ((size_t)z * NPIX + n0) * KDIM;

    float acc[4][4][4];
    #pragma unroll
    for (int i = 0; i < 4; i++)
        #pragma unroll
        for (int j = 0; j < 4; j++)
            #pragma unroll
            for (int k = 0; k < 4; k++) acc[i][j][k] = 0.f;

    gemm_load_stage(sm, 0, 0, tid, a0p, b0p);
    gemm_load_stage(sm, 1, 1, tid, a0p, b0p);

    int a_row = wm * 64 + ((lane >> 3) & 1) * 8 + (lane & 7);
    int a_ck  = (lane >> 4);
    int b_row = wn * 32 + (lane >> 4) * 8 + (lane & 7);
    int b_ck  = ((lane >> 3) & 1);
    uint32_t sbase = smem_u32(sm);

    for (int ck = 0; ck < 8; ck++) {
        if (ck + 2 < 8) {
            gemm_load_stage(sm, (ck + 2) % 3, ck + 2, tid, a0p, b0p);
            CP_WAIT(2);
        } else if (ck + 1 < 8) {
            CP_WAIT(1);
        } else {
            CP_WAIT(0);
        }
        __syncthreads();

        uint32_t st = sbase + (ck % 3) * STG;
        #pragma unroll
        for (int kk = 0; kk < 4; kk++) {
            uint32_t af[4][4];
            #pragma unroll
            for (int mf = 0; mf < 4; mf++) {
                int row = a_row + mf * 16;
                int chv = (kk * 2 + a_ck) ^ (row & 7);
                LDSM4(af[mf], st + row * 128 + (chv << 4));
            }
            uint32_t bf[2][4];
            #pragma unroll
            for (int ng = 0; ng < 2; ng++) {
                int row = b_row + ng * 16;
                int chv = (kk * 2 + b_ck) ^ (row & 7);
                LDSM4(bf[ng], st + 16384 + row * 128 + (chv << 4));
            }
            #pragma unroll
            for (int mf = 0; mf < 4; mf++)
                #pragma unroll
                for (int ng = 0; ng < 2; ng++)
                    #pragma unroll
                    for (int nh = 0; nh < 2; nh++)
                        MMA16816(acc[mf][ng * 2 + nh], af[mf],
                                 bf[ng][nh * 2], bf[ng][nh * 2 + 1]);
        }
        __syncthreads();
    }

    size_t obase = (size_t)z * M * NPIX;
    if (Ch) {
        #pragma unroll
        for (int mf = 0; mf < 4; mf++) {
            int m = m0 + wm * 64 + mf * 16 + (lane >> 2);
            #pragma unroll
            for (int nf = 0; nf < 4; nf++) {
                int n = n0 + wn * 32 + nf * 8 + (lane & 3) * 2;
                *(__half2*)&Ch[obase + (size_t)m * NPIX + n] =
                    __floats2half2_rn(acc[mf][nf][0], acc[mf][nf][1]);
                *(__half2*)&Ch[obase + (size_t)(m + 8) * NPIX + n] =
                    __floats2half2_rn(acc[mf][nf][2], acc[mf][nf][3]);
            }
        }
    } else {
        #pragma unroll
        for (int mf = 0; mf < 4; mf++) {
            int m = m0 + wm * 64 + mf * 16 + (lane >> 2);
            float bb0 = bias ? bias[m] : 0.f;
            float bb8 = bias ? bias[m + 8] : 0.f;
            #pragma unroll
            for (int nf = 0; nf < 4; nf++) {
                int n = n0 + wn * 32 + nf * 8 + (lane & 3) * 2;
                *(float2*)&Cf[obase + (size_t)m * NPIX + n] =
                    make_float2(acc[mf][nf][0] + bb0, acc[mf][nf][1] + bb0);
                *(float2*)&Cf[obase + (size_t)(m + 8) * NPIX + n] =
                    make_float2(acc[mf][nf][2] + bb8, acc[mf][nf][3] + bb8);
            }
        }
    }
}

// ---------------------------------------------------------------------------
// qlhat: normalized latent queries (batch-invariant). grid=8, 256 threads.
// ---------------------------------------------------------------------------
__global__ __launch_bounds__(256) void qlhat_kernel(
    const float* __restrict__ w_q_lat, const float* __restrict__ latents,
    float* __restrict__ qlhat)
{
    int h = blockIdx.x;
    __shared__ float slat[C][L];
    __shared__ float stile[DH][L];
    __shared__ float snorm[L];
    int tid = threadIdx.x;
    for (int i = tid; i < C * L; i += 256) slat[i >> 4][i & 15] = latents[i];
    __syncthreads();
    for (int p = tid; p < DH * L; p += 256) {
        int j = p >> 4, l = p & 15;
        const float* wrow = w_q_lat + (size_t)(h * DH + j) * C;
        float acc = 0.f;
        for (int c2 = 0; c2 < C; c2++) acc += wrow[c2] * slat[c2][l];
        stile[j][l] = acc;
    }
    __syncthreads();
    if (tid < L) {
        float s = 0.f;
        for (int j = 0; j < DH; j++) { float v = stile[j][tid]; s += v * v; }
        snorm[tid] = 1.f / fmaxf(sqrtf(s), EPSN);
    }
    __syncthreads();
    for (int p = tid; p < DH * L; p += 256)
        qlhat[(h * DH + (p >> 4)) * L + (p & 15)] = stile[p >> 4][p & 15] * snorm[p & 15];
}

// ---------------------------------------------------------------------------
// attn1 fused: per (bh, split of 1024 px): exp(logits) -> smem tile [16][1024],
// per-split L-sums -> lsum_g, unnormalized partial P@V -> latpart.
// grid (64, 4), 512 threads, ~69KB dynamic smem.
// ---------------------------------------------------------------------------
__global__ __launch_bounds__(512) void attn1_fused_kernel(
    const __half* __restrict__ kvq, const float* __restrict__ qlhat,
    float* __restrict__ latpart, float* __restrict__ lsum_g)
{
    extern __shared__ float dyn[];
    float* p_sm = dyn;                       // [16][1024] = 64KB
    float (*sql)[L] = (float(*)[L])(dyn + L * 1024);   // [64][16]
    float (*wred)[L] = (float(*)[L])(dyn + L * 1024 + DH * L); // [16][16]

    int bh = blockIdx.x, split = blockIdx.y, b = bh >> 3, h = bh & 7;
    const __half* kbase = kvq + ((size_t)b * MROWS + h * DH) * NPIX + split * 1024;
    const __half* vbase = kvq + ((size_t)b * MROWS + 512 + h * DH) * NPIX + split * 1024;
    int tid = threadIdx.x, lane = tid & 31, wrp = tid >> 5;

    for (int i = tid; i < DH * L; i += 512)
        sql[i >> 4][i & 15] = qlhat[(h * DH + (i >> 4)) * L + (i & 15)];
    __syncthreads();

    // phase 1: 2 pixels per thread (2*tid, 2*tid+1)
    {
        float dot[2][L], nrm[2] = {0.f, 0.f};
        #pragma unroll
        for (int i = 0; i < 2; i++)
            #pragma unroll
            for (int l = 0; l < L; l++) dot[i][l] = 0.f;
        for (int j = 0; j < DH; j++) {
            __half2 a01 = *(const __half2*)(kbase + (size_t)j * NPIX + 2 * tid);
            float k0 = __low2float(a01), k1 = __high2float(a01);
            nrm[0] += k0 * k0; nrm[1] += k1 * k1;
            #pragma unroll
            for (int l = 0; l < L; l++) {
                float s = sql[j][l];
                dot[0][l] += k0 * s;
                dot[1][l] += k1 * s;
            }
        }
        float inv0 = SCALE / fmaxf(sqrtf(nrm[0]), EPSN);
        float inv1 = SCALE / fmaxf(sqrtf(nrm[1]), EPSN);
        float lsum[L];
        #pragma unroll
        for (int l = 0; l < L; l++) {
            float p0 = __expf(dot[0][l] * inv0);
            float p1 = __expf(dot[1][l] * inv1);
            lsum[l] = p0 + p1;
            *(float2*)&p_sm[l * 1024 + 2 * tid] = make_float2(p0, p1);
        }
        #pragma unroll
        for (int l = 0; l < L; l++) {
            float v = lsum[l];
            #pragma unroll
            for (int o = 16; o; o >>= 1) v += __shfl_xor_sync(0xffffffffu, v, o);
            if (lane == 0) wred[wrp][l] = v;
        }
    }
    __syncthreads();
    if (tid < L) {
        float s = 0.f;
        #pragma unroll
        for (int w = 0; w < 16; w++) s += wred[w][tid];
        lsum_g[bh * 64 + split * 16 + tid] = s;
    }

    // phase 2: warp wrp owns rows j in [4*wrp, 4*wrp+4); unnormalized P@V
    float acc[4][L];
    #pragma unroll
    for (int jj = 0; jj < 4; jj++)
        #pragma unroll
        for (int l = 0; l < L; l++) acc[jj][l] = 0.f;

    for (int it = 0; it < 16; it++) {
        int n2 = it * 64 + lane * 2;
        float2 pv[L];
        #pragma unroll
        for (int l = 0; l < L; l++) pv[l] = *(const float2*)&p_sm[l * 1024 + n2];
        #pragma unroll
        for (int jj = 0; jj < 4; jj++) {
            __half2 v2 = *(const __half2*)&vbase[(size_t)(wrp * 4 + jj) * NPIX + n2];
            float v0 = __low2float(v2), v1 = __high2float(v2);
            #pragma unroll
            for (int l = 0; l < L; l++) acc[jj][l] += v0 * pv[l].x + v1 * pv[l].y;
        }
    }
    #pragma unroll
    for (int jj = 0; jj < 4; jj++)
        #pragma unroll
        for (int l = 0; l < L; l++) {
            float v = acc[jj][l];
            #pragma unroll
            for (int o = 16; o; o >>= 1) v += __shfl_xor_sync(0xffffffffu, v, o);
            if (lane == 0)
                latpart[split * 65536 + bh * 1024 + (wrp * 4 + jj) * 16 + l] = v;
        }
}

// attn1d: reduce splits, compute sinv inline, scale -> latread. grid 256x256.
__global__ __launch_bounds__(256) void attn1d_kernel(
    const float* __restrict__ latpart, const float* __restrict__ lsum_g,
    float* __restrict__ latread)
{
    int e = blockIdx.x * 256 + threadIdx.x;
    int bh = e >> 10, rem = e & 1023, r = rem >> 4, l = rem & 15;
    float s = latpart[e] + latpart[65536 + e] + latpart[131072 + e] + latpart[196608 + e];
    float d = lsum_g[bh * 64 + l] + lsum_g[bh * 64 + 16 + l] +
              lsum_g[bh * 64 + 32 + l] + lsum_g[bh * 64 + 48 + l];
    int b = bh >> 3, h = bh & 7;
    latread[((size_t)b * C + h * DH + r) * L + l] = s / d;
}

// ---------------------------------------------------------------------------
// kvl: kvl[b] = w_kv_lat @ lat_read[b]; normalize k-part per (head,l).
// ---------------------------------------------------------------------------
__global__ __launch_bounds__(256) void kvl_kernel(
    const float* __restrict__ w_kv_lat, const float* __restrict__ latread,
    float* __restrict__ kvl)
{
    int b = blockIdx.x, c0 = blockIdx.y * 64;
    __shared__ float slat[C][L];
    __shared__ float stile[64][L];
    __shared__ float snorm[L];
    int tid = threadIdx.x;
    const float* lr = latread + (size_t)b * C * L;
    for (int i = tid; i < C * L; i += 256) slat[i >> 4][i & 15] = lr[i];
    __syncthreads();
    for (int p = tid; p < 64 * L; p += 256) {
        int j = p >> 4, l = p & 15;
        const float* wrow = w_kv_lat + (size_t)(c0 + j) * C;
        float acc = 0.f;
        for (int c2 = 0; c2 < C; c2++) acc += wrow[c2] * slat[c2][l];
        stile[j][l] = acc;
    }
    __syncthreads();
    if (c0 < C) {
        if (tid < L) {
            float s = 0.f;
            for (int j = 0; j < 64; j++) { float v = stile[j][tid]; s += v * v; }
            snorm[tid] = 1.f / fmaxf(sqrtf(s), EPSN);
        }
        __syncthreads();
        for (int p = tid; p < 64 * L; p += 256)
            kvl[((size_t)b * 2 * C + c0 + (p >> 4)) * L + (p & 15)] =
                stile[p >> 4][p & 15] * snorm[p & 15];
    } else {
        for (int p = tid; p < 64 * L; p += 256)
            kvl[((size_t)b * 2 * C + c0 + (p >> 4)) * L + (p & 15)] = stile[p >> 4][p & 15];
    }
}

// ---------------------------------------------------------------------------
// attn2: latent write; 2 pixels/thread via half2 q loads; fp16 xwT out.
// grid (16, HEADS, Bsz), 128 threads (256 px/block).
// ---------------------------------------------------------------------------
__global__ __launch_bounds__(128) void attn2_kernel(
    const __half* __restrict__ kvq, const float* __restrict__ kvl,
    __half* __restrict__ xwT)
{
    int b = blockIdx.z, h = blockIdx.y;
    int tid = threadIdx.x;
    int n = blockIdx.x * 256 + 2 * tid;   // pixels n, n+1
    __shared__ float skl[DH][L];
    __shared__ float svl[DH][L];
    __shared__ unsigned short sh[DH][256];

    const float* kvlb = kvl + (size_t)b * 2 * C * L;
    for (int i = tid; i < DH * L; i += 128) {
        skl[i >> 4][i & 15] = kvlb[(h * DH + (i >> 4)) * L + (i & 15)];
        svl[i >> 4][i & 15] = kvlb[(C + h * DH + (i >> 4)) * L + (i & 15)];
    }
    __syncthreads();

    const __half* qcol = kvq + ((size_t)b * MROWS + 1024 + h * DH) * NPIX + n;
    float dot[2][L], nrm[2] = {0.f, 0.f};
    #pragma unroll
    for (int i = 0; i < 2; i++)
        #pragma unroll
        for (int l = 0; l < L; l++) dot[i][l] = 0.f;
    for (int j = 0; j < DH; j++) {
        __half2 q2 = *(const __half2*)(qcol + (size_t)j * NPIX);
        float q0 = __low2float(q2), q1 = __high2float(q2);
        nrm[0] += q0 * q0; nrm[1] += q1 * q1;
        #pragma unroll
        for (int l = 0; l < L; l++) {
            float s = skl[j][l];
            dot[0][l] += q0 * s;
            dot[1][l] += q1 * s;
        }
    }
    float is[2];
    #pragma unroll
    for (int i = 0; i < 2; i++) {
        float inv = SCALE / fmaxf(sqrtf(nrm[i]), EPSN);
        float s = 0.f;
        #pragma unroll
        for (int l = 0; l < L; l++) { dot[i][l] = __expf(dot[i][l] * inv); s += dot[i][l]; }
        is[i] = 1.f / s;
    }

    for (int j = 0; j < DH; j++) {
        float a0 = 0.f, a1 = 0.f;
        #pragma unroll
        for (int l = 0; l < L; l++) {
            float v = svl[j][l];
            a0 += dot[0][l] * v;
            a1 += dot[1][l] * v;
        }
        sh[j][2 * tid]     = __half_as_ushort(__float2half_rn(a0 * is[0]));
        sh[j][2 * tid + 1] = __half_as_ushort(__float2half_rn(a1 * is[1]));
    }
    __syncthreads();

    // write both pixels' channel blocks, coalesced 16B per pixel row
    #pragma unroll
    for (int px = 0; px < 2; px++) {
        int pp = 2 * tid + px;
        int np = blockIdx.x * 256 + pp;
        size_t base = ((size_t)b * NPIX + np) * C + h * DH;
        #pragma unroll
        for (int c4 = 0; c4 < 8; c4++) {
            uint32_t wv[4];
            #pragma unroll
            for (int k = 0; k < 4; k++) {
                int j = c4 * 8 + k * 2;
                wv[k] = (uint32_t)sh[j][pp] | ((uint32_t)sh[j + 1][pp] << 16);
            }
            *(uint4*)(xwT + base + c4 * 8) = make_uint4(wv[0], wv[1], wv[2], wv[3]);
        }
    }
}

// ---------------------------------------------------------------------------
// Launch (side stream overlaps w_proj conv + qlhat with the main chain)
// ---------------------------------------------------------------------------
extern "C" void kernel_launch(void* const* d_in, const int* in_sizes, int n_in,
                              void* d_out, int out_size)
{
    const float* x        = (const float*)d_in[0];
    const float* latents  = (const float*)d_in[1];
    const float* w_q_lat  = (const float*)d_in[2];
    const float* w_kv_x   = (const float*)d_in[3];
    const float* w_q_x    = (const float*)d_in[4];
    const float* w_kv_lat = (const float*)d_in[5];
    const float* w_proj   = (const float*)d_in[6];
    const float* b_proj   = (const float*)d_in[7];
    float* out = (float*)d_out;

    float *lsum, *latpart, *latread, *kvl, *qlhat;
    __half *kvq, *xT, *xwT, *wA, *wp;
    cudaGetSymbolAddress((void**)&kvq, g_kvq);
    cudaGetSymbolAddress((void**)&lsum, g_lsum);
    cudaGetSymbolAddress((void**)&latpart, g_latpart);
    cudaGetSymbolAddress((void**)&latread, g_latread);
    cudaGetSymbolAddress((void**)&kvl, g_kvl);
    cudaGetSymbolAddress((void**)&qlhat, g_qlhat);
    cudaGetSymbolAddress((void**)&xT, g_xT);
    cudaGetSymbolAddress((void**)&xwT, g_xwT);
    cudaGetSymbolAddress((void**)&wA, g_wA);
    cudaGetSymbolAddress((void**)&wp, g_wp);

    static cudaStream_t s1 = nullptr;
    static cudaEvent_t evFork = nullptr, evSide = nullptr;
    if (!s1) {
        cudaStreamCreateWithFlags(&s1, cudaStreamNonBlocking);
        cudaEventCreateWithFlags(&evFork, cudaEventDisableTiming);
        cudaEventCreateWithFlags(&evSide, cudaEventDisableTiming);
    }

    cudaFuncSetAttribute(gemm_mma, cudaFuncAttributeMaxDynamicSharedMemorySize, 3 * STG);
    int attn1_smem = (L * 1024 + DH * L + 16 * L) * sizeof(float);
    cudaFuncSetAttribute(attn1_fused_kernel, cudaFuncAttributeMaxDynamicSharedMemorySize, attn1_smem);

    // fork side stream: proj-weight conversion + qlhat (consumed later)
    cudaEventRecord(evFork, 0);
    cudaStreamWaitEvent(s1, evFork, 0);
    wconv_kernel<<<(C * KDIM / 4 + 255) / 256, 256, 0, s1>>>(w_proj, wp, C * KDIM / 4);
    qlhat_kernel<<<HEADS, 256, 0, s1>>>(w_q_lat, latents, qlhat);
    cudaEventRecord(evSide, s1);

    // main chain
    wconv_kernel<<<(2 * C * KDIM / 4 + 255) / 256, 256>>>(w_kv_x, wA, 2 * C * KDIM / 4);
    wconv_kernel<<<(C * KDIM / 4 + 255) / 256, 256>>>(w_q_x, wA + 2 * C * KDIM, C * KDIM / 4);
    tconv_kernel<<<dim3(NPIX / 32, C / 32, Bsz), dim3(32, 8)>>>(x, xT);

    // fused kv+q GEMM (M=1536) -> fp16 kvq
    gemm_mma<<<dim3(32, 12, Bsz), 256, 3 * STG>>>(wA, xT, kvq, nullptr, nullptr, MROWS);

    // join side stream (qlhat needed by attn1, wp needed by final gemm)
    cudaStreamWaitEvent(0, evSide, 0);

    // latent read attention (fused exp + partial P@V)
    attn1_fused_kernel<<<dim3(64, 4), 512, attn1_smem>>>(kvq, qlhat, latpart, lsum);
    attn1d_kernel<<<256, 256>>>(latpart, lsum, latread);

    kvl_kernel<<<dim3(Bsz, 16), 256>>>(w_kv_lat, latread, kvl);

    // latent write attention -> fp16 xwT
    attn2_kernel<<<dim3(16, HEADS, Bsz), 128>>>(kvq, kvl, xwT);

    // output projection + bias (fp32 out)
    gemm_mma<<<dim3(32, 4, Bsz), 256, 3 * STG>>>(wp, xwT, nullptr, out, b_proj, 512);
}